// round 1
// baseline (speedup 1.0000x reference)
#include <cuda_runtime.h>
#include <cstdint>
#include <cstddef>

// Problem constants (fixed by the dataset)
#define BB    8
#define SQ    4096
#define QD    1280
#define SCTX  93
#define CD    2048
#define NH    20
#define DH    64
#define INNER 1280   // NH*DH

// ---------------------------------------------------------------------------
// Scratch (no allocs allowed -> __device__ globals)
// ---------------------------------------------------------------------------
__device__ float g_q[(size_t)BB * NH * SQ * DH];      // Q in [b,h,s,d]   (167.8 MB)
__device__ float g_attn[(size_t)BB * SQ * INNER];     // attn out [b,s,i] (167.8 MB)
__device__ float g_k[(size_t)BB * NH * SCTX * DH];    // K  [b,h,s,d] (txt rows use Wk, img rows Wk_ip)
__device__ float g_v[(size_t)BB * NH * SCTX * DH];    // V  [b,h,s,d]

// ---------------------------------------------------------------------------
// Kernel 1: KV projections.
//   k[b,h,s,d] = sum_c ctx[b,s,c] * (s<eos ? Wk : Wk_ip)[h*64+d, c]   (v likewise)
// Grid: (NH, BB), 512 threads. Block computes one (b, head): 93 x 64 outputs
// for both K and V, streaming ctx + 4 weight tiles through smem.
// ---------------------------------------------------------------------------
__global__ void __launch_bounds__(512) kv_proj_kernel(
    const float* __restrict__ ctx,
    const float* __restrict__ Wk,  const float* __restrict__ Wv,
    const float* __restrict__ Wki, const float* __restrict__ Wvi,
    const int*   __restrict__ nimg_p)
{
    __shared__ float cs[96][17];
    __shared__ float wk_s[64][17], wv_s[64][17], wki_s[64][17], wvi_s[64][17];

    const int tid = threadIdx.x;
    const int b   = blockIdx.y;
    const int hh  = blockIdx.x;          // head index == 64-wide n tile
    const int n0  = hh * 64;
    const int eos = SCTX - *nimg_p;
    const int n   = tid & 63;            // 0..63 output dim within head
    const int g   = tid >> 6;            // 0..7 row group, 12 s-rows each

    float ak[12], av[12];
#pragma unroll
    for (int j = 0; j < 12; ++j) { ak[j] = 0.f; av[j] = 0.f; }

    for (int k0 = 0; k0 < CD; k0 += 16) {
        __syncthreads();
        // ctx chunk [96][16] (rows >= SCTX zero-filled)
        for (int i = tid; i < 96 * 16; i += 512) {
            int s = i >> 4, kk = i & 15;
            cs[s][kk] = (s < SCTX)
                ? ctx[((size_t)b * SCTX + s) * CD + k0 + kk] : 0.f;
        }
        // weight chunks [64][16] x 4 matrices
        for (int i = tid; i < 64 * 16; i += 512) {
            int r = i >> 4, kk = i & 15;
            size_t gi = (size_t)(n0 + r) * CD + k0 + kk;
            wk_s [r][kk] = Wk [gi];
            wv_s [r][kk] = Wv [gi];
            wki_s[r][kk] = Wki[gi];
            wvi_s[r][kk] = Wvi[gi];
        }
        __syncthreads();
#pragma unroll
        for (int kk = 0; kk < 16; ++kk) {
            float wkv  = wk_s [n][kk];
            float wvv  = wv_s [n][kk];
            float wkiv = wki_s[n][kk];
            float wviv = wvi_s[n][kk];
#pragma unroll
            for (int j = 0; j < 12; ++j) {
                int s = g * 12 + j;
                float c = cs[s][kk];
                bool txt = (s < eos);
                ak[j] = fmaf(c, txt ? wkv : wkiv, ak[j]);
                av[j] = fmaf(c, txt ? wvv : wviv, av[j]);
            }
        }
    }

    size_t base = ((size_t)(b * NH + hh) * SCTX) * DH + n;
#pragma unroll
    for (int j = 0; j < 12; ++j) {
        int s = g * 12 + j;
        if (s < SCTX) {
            g_k[base + (size_t)s * DH] = ak[j];
            g_v[base + (size_t)s * DH] = av[j];
        }
    }
}

// ---------------------------------------------------------------------------
// Kernel 2: fp32 SGEMM  C[m,n] = sum_k A[m,k] * W[n,k]  (+ bias[n])
// Both big GEMMs: M = 32768, N = 1280, K passed (1280). BM=BN=128, BK=8,
// 256 threads, 8x8 per-thread microtile.
// REMAP_Q: scatter output into g_q's [b,h,s,d] layout instead of row-major.
// ---------------------------------------------------------------------------
template <bool REMAP_Q, bool HAS_BIAS>
__global__ void __launch_bounds__(256, 2) sgemm_nt(
    const float* __restrict__ A, const float* __restrict__ W,
    const float* __restrict__ bias, float* __restrict__ C, int K)
{
    __shared__ float As[8][128];
    __shared__ float Bs[8][128];

    const int tid  = threadIdx.x;
    const int m0   = blockIdx.y << 7;
    const int n0   = blockIdx.x << 7;
    const int ty   = tid >> 4;       // 0..15 -> 8 rows each
    const int tx   = tid & 15;       // 0..15 -> 8 cols each
    const int lrow = tid >> 1;       // 0..127
    const int lk   = (tid & 1) << 2; // 0 or 4

    const float* Ag = A + (size_t)(m0 + lrow) * K + lk;
    const float* Wg = W + (size_t)(n0 + lrow) * K + lk;

    float acc[8][8];
#pragma unroll
    for (int i = 0; i < 8; ++i)
#pragma unroll
        for (int j = 0; j < 8; ++j) acc[i][j] = 0.f;

    for (int k0 = 0; k0 < K; k0 += 8) {
        float4 a4 = *(const float4*)(Ag + k0);
        float4 w4 = *(const float4*)(Wg + k0);
        __syncthreads();
        As[lk + 0][lrow] = a4.x; As[lk + 1][lrow] = a4.y;
        As[lk + 2][lrow] = a4.z; As[lk + 3][lrow] = a4.w;
        Bs[lk + 0][lrow] = w4.x; Bs[lk + 1][lrow] = w4.y;
        Bs[lk + 2][lrow] = w4.z; Bs[lk + 3][lrow] = w4.w;
        __syncthreads();
#pragma unroll
        for (int kk = 0; kk < 8; ++kk) {
            float4 a0 = *(const float4*)&As[kk][ty * 8 + 0];
            float4 a1 = *(const float4*)&As[kk][ty * 8 + 4];
            float4 b0 = *(const float4*)&Bs[kk][tx * 8 + 0];
            float4 b1 = *(const float4*)&Bs[kk][tx * 8 + 4];
            float a[8] = {a0.x, a0.y, a0.z, a0.w, a1.x, a1.y, a1.z, a1.w};
            float bb[8] = {b0.x, b0.y, b0.z, b0.w, b1.x, b1.y, b1.z, b1.w};
#pragma unroll
            for (int i = 0; i < 8; ++i)
#pragma unroll
                for (int j = 0; j < 8; ++j)
                    acc[i][j] = fmaf(a[i], bb[j], acc[i][j]);
        }
    }

#pragma unroll
    for (int i = 0; i < 8; ++i) {
        int m = m0 + ty * 8 + i;
#pragma unroll
        for (int j = 0; j < 8; j += 4) {
            int n = n0 + tx * 8 + j;
            float4 v;
            v.x = acc[i][j];     v.y = acc[i][j + 1];
            v.z = acc[i][j + 2]; v.w = acc[i][j + 3];
            if (HAS_BIAS) {
                v.x += bias[n];     v.y += bias[n + 1];
                v.z += bias[n + 2]; v.w += bias[n + 3];
            }
            if (REMAP_Q) {
                int bb_ = m >> 12, s = m & 4095;
                int h = n >> 6,  d = n & 63;
                *(float4*)(C + (((size_t)(bb_ * NH + h) * SQ + s) * DH + d)) = v;
            } else {
                *(float4*)(C + (size_t)m * INNER + n) = v;
            }
        }
    }
}

// ---------------------------------------------------------------------------
// Kernel 3: two-segment softmax attention, fused.
// Block: 256 q-rows of one (b,h). K/V (93x64 each) + per-thread logit rows in
// dynamic smem; q and out live in registers. out = softmax(qK_t^T/8)V_t
//                                                 + scale * softmax(qK_i^T/8)V_i
// ---------------------------------------------------------------------------
#define ATTN_SMEM_FLOATS (2 * SCTX * DH + 256 * 97)
#define ATTN_SMEM_BYTES  (ATTN_SMEM_FLOATS * 4)

__global__ void __launch_bounds__(256) attn_kernel(
    const float* __restrict__ scale_p, const int* __restrict__ nimg_p)
{
    extern __shared__ float sm[];
    float* Ks = sm;                         // [93][64]
    float* Vs = sm + SCTX * DH;             // [93][64]
    float* Ls = sm + 2 * SCTX * DH;         // [256][97] logits / [256][65] staging

    const int tid = threadIdx.x;
    const int bh  = blockIdx.x;             // b*NH + h
    const int q0  = blockIdx.y << 8;
    const int b   = bh / NH;
    const int h   = bh % NH;
    const int eos = SCTX - *nimg_p;
    const float ipscale = *scale_p;

    // K/V tiles (coalesced float4)
    const float4* kg = (const float4*)(g_k + (size_t)bh * SCTX * DH);
    const float4* vg = (const float4*)(g_v + (size_t)bh * SCTX * DH);
    float4* K4 = (float4*)Ks;
    float4* V4 = (float4*)Vs;
    for (int i = tid; i < SCTX * DH / 4; i += 256) { K4[i] = kg[i]; V4[i] = vg[i]; }

    // q: coalesced global -> smem staging -> regs (pad 65 => conflict-free)
    const float* qg = g_q + ((size_t)bh * SQ + q0) * DH;
    for (int i = tid; i < 256 * DH; i += 256) {
        int r = i >> 6, d = i & 63;
        Ls[r * 65 + d] = qg[i];
    }
    __syncthreads();
    float q[64];
#pragma unroll
    for (int d = 0; d < 64; ++d) q[d] = Ls[tid * 65 + d];
    __syncthreads();

    // pass 1: logits  (pad 97 => stride%32==1, conflict-free per-thread rows)
    float* Lrow = Ls + tid * 97;
    for (int s = 0; s < SCTX; ++s) {
        const float4* krow = K4 + s * 16;
        float acc = 0.f;
#pragma unroll
        for (int d4 = 0; d4 < 16; ++d4) {
            float4 kv = krow[d4];
            acc = fmaf(q[d4 * 4 + 0], kv.x, acc);
            acc = fmaf(q[d4 * 4 + 1], kv.y, acc);
            acc = fmaf(q[d4 * 4 + 2], kv.z, acc);
            acc = fmaf(q[d4 * 4 + 3], kv.w, acc);
        }
        Lrow[s] = acc * 0.125f;   // 1/sqrt(64)
    }

    // segment softmax stats
    float m1 = -1e30f, m2 = -1e30f;
    for (int s = 0;   s < eos;  ++s) m1 = fmaxf(m1, Lrow[s]);
    for (int s = eos; s < SCTX; ++s) m2 = fmaxf(m2, Lrow[s]);
    float d1 = 0.f, d2 = 0.f;
    for (int s = 0;   s < eos;  ++s) d1 += __expf(Lrow[s] - m1);
    for (int s = eos; s < SCTX; ++s) d2 += __expf(Lrow[s] - m2);
    float w1 = 1.f / d1;
    float w2 = (eos < SCTX && d2 > 0.f) ? (ipscale / d2) : 0.f;

    // pass 2: out = sum_s w_s * V[s]
    float o[64];
#pragma unroll
    for (int d = 0; d < 64; ++d) o[d] = 0.f;
    for (int s = 0; s < SCTX; ++s) {
        float l = Lrow[s];
        float w = (s < eos) ? (__expf(l - m1) * w1) : (__expf(l - m2) * w2);
        const float4* vrow = V4 + s * 16;
#pragma unroll
        for (int d4 = 0; d4 < 16; ++d4) {
            float4 vv = vrow[d4];
            o[d4 * 4 + 0] = fmaf(w, vv.x, o[d4 * 4 + 0]);
            o[d4 * 4 + 1] = fmaf(w, vv.y, o[d4 * 4 + 1]);
            o[d4 * 4 + 2] = fmaf(w, vv.z, o[d4 * 4 + 2]);
            o[d4 * 4 + 3] = fmaf(w, vv.w, o[d4 * 4 + 3]);
        }
    }

    // stage out through smem for coalesced global store (row stride = INNER)
    __syncthreads();
#pragma unroll
    for (int d = 0; d < 64; ++d) Ls[tid * 65 + d] = o[d];
    __syncthreads();
    float* og = g_attn + ((size_t)b * SQ + q0) * INNER + h * DH;
    for (int i = tid; i < 256 * DH; i += 256) {
        int r = i >> 6, d = i & 63;
        og[(size_t)r * INNER + d] = Ls[r * 65 + d];
    }
}

// ---------------------------------------------------------------------------
// Launch
// Inputs (metadata order): x, context, scale, num_img_token,
//                          Wq, Wk, Wv, Wk_ip, Wv_ip, Wout, b_out
// ---------------------------------------------------------------------------
extern "C" void kernel_launch(void* const* d_in, const int* in_sizes, int n_in,
                              void* d_out, int out_size)
{
    const float* x     = (const float*)d_in[0];
    const float* ctx   = (const float*)d_in[1];
    const float* scale = (const float*)d_in[2];
    const int*   nimg  = (const int*)  d_in[3];
    const float* Wq    = (const float*)d_in[4];
    const float* Wk    = (const float*)d_in[5];
    const float* Wv    = (const float*)d_in[6];
    const float* Wki   = (const float*)d_in[7];
    const float* Wvi   = (const float*)d_in[8];
    const float* Wout  = (const float*)d_in[9];
    const float* bout  = (const float*)d_in[10];
    float*       out   = (float*)d_out;

    float *qp = nullptr, *ap = nullptr;
    cudaGetSymbolAddress((void**)&qp, g_q);
    cudaGetSymbolAddress((void**)&ap, g_attn);

    cudaFuncSetAttribute(attn_kernel,
                         cudaFuncAttributeMaxDynamicSharedMemorySize,
                         ATTN_SMEM_BYTES);

    // 1) K/V projections (text + image segments)
    kv_proj_kernel<<<dim3(NH, BB), 512>>>(ctx, Wk, Wv, Wki, Wvi, nimg);

    // 2) Q projection, scattered into [b,h,s,d]
    sgemm_nt<true, false><<<dim3(INNER / 128, (BB * SQ) / 128), 256>>>(
        x, Wq, nullptr, qp, QD);

    // 3) fused two-segment attention
    attn_kernel<<<dim3(BB * NH, SQ / 256), 256, ATTN_SMEM_BYTES>>>(scale, nimg);

    // 4) output projection + bias
    sgemm_nt<false, true><<<dim3(QD / 128, (BB * SQ) / 128), 256>>>(
        ap, Wout, bout, out, INNER);
}

// round 3
// speedup vs baseline: 1.8550x; 1.8550x over previous
#include <cuda_runtime.h>
#include <cuda_bf16.h>
#include <cstdint>
#include <cstddef>

// Problem constants
#define BB    8
#define SQ    4096
#define QD    1280
#define SCTX  93
#define CD    2048
#define NH    20
#define DH    64
#define INNER 1280

// ---------------------------------------------------------------------------
// Scratch (__device__ globals; no allocs allowed)
// ---------------------------------------------------------------------------
__device__ float         g_q  [(size_t)BB * NH * SQ * DH];   // Q fp32 [b,h,s,d]
__device__ __nv_bfloat16 g_xh [(size_t)BB * SQ * QD];
__device__ __nv_bfloat16 g_xl [(size_t)BB * SQ * QD];
__device__ __nv_bfloat16 g_ah [(size_t)BB * SQ * INNER];
__device__ __nv_bfloat16 g_al [(size_t)BB * SQ * INNER];
__device__ __nv_bfloat16 g_wqh[(size_t)INNER * QD];
__device__ __nv_bfloat16 g_wql[(size_t)INNER * QD];
__device__ __nv_bfloat16 g_woh[(size_t)QD * INNER];
__device__ __nv_bfloat16 g_wol[(size_t)QD * INNER];
__device__ float g_k[(size_t)BB * NH * SCTX * DH];
__device__ float g_v[(size_t)BB * NH * SCTX * DH];

// ---------------------------------------------------------------------------
// Helpers (arch-agnostic PTX only: cp.async, ldmatrix, mma.sync)
// ---------------------------------------------------------------------------
__device__ __forceinline__ uint32_t smem_u32(const void* p) {
    uint32_t a;
    asm("{ .reg .u64 t; cvta.to.shared.u64 t, %1; cvt.u32.u64 %0, t; }"
        : "=r"(a) : "l"(p));
    return a;
}
#define CP_COMMIT() asm volatile("cp.async.commit_group;" ::: "memory")
#define CP_WAIT(n)  asm volatile("cp.async.wait_group %0;" :: "n"(n) : "memory")

__device__ __forceinline__ void ldsm_x4(uint32_t addr, uint32_t& r0, uint32_t& r1,
                                        uint32_t& r2, uint32_t& r3) {
    asm volatile("ldmatrix.sync.aligned.m8n8.x4.shared.b16 {%0,%1,%2,%3}, [%4];"
                 : "=r"(r0), "=r"(r1), "=r"(r2), "=r"(r3) : "r"(addr));
}
__device__ __forceinline__ void mma_bf16(float* c, const uint32_t* a,
                                         const uint32_t* b) {
    asm volatile(
        "mma.sync.aligned.m16n8k16.row.col.f32.bf16.bf16.f32 "
        "{%0,%1,%2,%3}, {%4,%5,%6,%7}, {%8,%9}, {%0,%1,%2,%3};"
        : "+f"(c[0]), "+f"(c[1]), "+f"(c[2]), "+f"(c[3])
        : "r"(a[0]), "r"(a[1]), "r"(a[2]), "r"(a[3]), "r"(b[0]), "r"(b[1]));
}

// ---------------------------------------------------------------------------
// fp32 -> bf16 hi/lo split
// ---------------------------------------------------------------------------
__global__ void split_bf16(const float4* __restrict__ src,
                           ushort4* __restrict__ hi, ushort4* __restrict__ lo,
                           int n4)
{
    for (int i = blockIdx.x * blockDim.x + threadIdx.x; i < n4;
         i += gridDim.x * blockDim.x) {
        float4 v = src[i];
        __nv_bfloat16 h0 = __float2bfloat16(v.x), h1 = __float2bfloat16(v.y);
        __nv_bfloat16 h2 = __float2bfloat16(v.z), h3 = __float2bfloat16(v.w);
        ushort4 H, L;
        H.x = __bfloat16_as_ushort(h0); H.y = __bfloat16_as_ushort(h1);
        H.z = __bfloat16_as_ushort(h2); H.w = __bfloat16_as_ushort(h3);
        L.x = __bfloat16_as_ushort(__float2bfloat16(v.x - __bfloat162float(h0)));
        L.y = __bfloat16_as_ushort(__float2bfloat16(v.y - __bfloat162float(h1)));
        L.z = __bfloat16_as_ushort(__float2bfloat16(v.z - __bfloat162float(h2)));
        L.w = __bfloat16_as_ushort(__float2bfloat16(v.w - __bfloat162float(h3)));
        hi[i] = H; lo[i] = L;
    }
}

// ---------------------------------------------------------------------------
// KV projections (fp32, small)
// ---------------------------------------------------------------------------
__global__ void __launch_bounds__(512) kv_proj_kernel(
    const float* __restrict__ ctx,
    const float* __restrict__ Wk,  const float* __restrict__ Wv,
    const float* __restrict__ Wki, const float* __restrict__ Wvi,
    const int*   __restrict__ nimg_p)
{
    __shared__ float cs[96][17];
    __shared__ float wk_s[64][17], wv_s[64][17], wki_s[64][17], wvi_s[64][17];

    const int tid = threadIdx.x;
    const int b   = blockIdx.y;
    const int hh  = blockIdx.x;
    const int n0  = hh * 64;
    const int eos = SCTX - *nimg_p;
    const int n   = tid & 63;
    const int g   = tid >> 6;

    float ak[12], av[12];
#pragma unroll
    for (int j = 0; j < 12; ++j) { ak[j] = 0.f; av[j] = 0.f; }

    for (int k0 = 0; k0 < CD; k0 += 16) {
        __syncthreads();
        for (int i = tid; i < 96 * 16; i += 512) {
            int s = i >> 4, kk = i & 15;
            cs[s][kk] = (s < SCTX) ? ctx[((size_t)b * SCTX + s) * CD + k0 + kk] : 0.f;
        }
        for (int i = tid; i < 64 * 16; i += 512) {
            int r = i >> 4, kk = i & 15;
            size_t gi = (size_t)(n0 + r) * CD + k0 + kk;
            wk_s [r][kk] = Wk [gi]; wv_s [r][kk] = Wv [gi];
            wki_s[r][kk] = Wki[gi]; wvi_s[r][kk] = Wvi[gi];
        }
        __syncthreads();
#pragma unroll
        for (int kk = 0; kk < 16; ++kk) {
            float wkv = wk_s[n][kk],  wvv = wv_s[n][kk];
            float wkiv = wki_s[n][kk], wviv = wvi_s[n][kk];
#pragma unroll
            for (int j = 0; j < 12; ++j) {
                int s = g * 12 + j;
                float c = cs[s][kk];
                bool txt = (s < eos);
                ak[j] = fmaf(c, txt ? wkv : wkiv, ak[j]);
                av[j] = fmaf(c, txt ? wvv : wviv, av[j]);
            }
        }
    }
    size_t base = ((size_t)(b * NH + hh) * SCTX) * DH + n;
#pragma unroll
    for (int j = 0; j < 12; ++j) {
        int s = g * 12 + j;
        if (s < SCTX) {
            g_k[base + (size_t)s * DH] = ak[j];
            g_v[base + (size_t)s * DH] = av[j];
        }
    }
}

// ---------------------------------------------------------------------------
// HMMA bf16x3 GEMM: C[m,n] = sum_k A[m,k]*B[n,k], A=Ah+Al, B=Bh+Bl.
// 128x128 CTA tile, 8 warps (2m x 4n), 64x32 warp tile, K-chunk 64,
// 3-stage cp.async pipeline. mma.sync m16n8k16 bf16 (compute_103-safe).
// ---------------------------------------------------------------------------
#define GEMM_STAGES 3
#define TILE_BYTES  16384                 // one 128x64 bf16 tile
#define STAGE_BYTES (4 * TILE_BYTES)      // Ah, Al, Bh, Bl
#define GEMM_SMEM   (GEMM_STAGES * STAGE_BYTES)

__device__ __forceinline__ void load_tiles(
    uint32_t sbase,
    const __nv_bfloat16* __restrict__ Ah, const __nv_bfloat16* __restrict__ Al,
    const __nv_bfloat16* __restrict__ Bh, const __nv_bfloat16* __restrict__ Bl,
    int m0, int n0, int k0, int K, int tid)
{
#pragma unroll
    for (int i = 0; i < 16; ++i) {
        int idx = tid + (i << 8);            // 0..4095 16B chunks
        int mat = idx >> 10;                 // 0:Ah 1:Al 2:Bh 3:Bl
        int r   = (idx >> 3) & 127;
        int cb  = idx & 7;
        int grow = ((mat < 2) ? m0 : n0) + r;
        const __nv_bfloat16* base = (mat == 0) ? Ah : (mat == 1) ? Al
                                  : (mat == 2) ? Bh : Bl;
        const char* src = (const char*)(base + (size_t)grow * K + k0) + (cb << 4);
        int boff = (r << 7) + (cb << 4);
        uint32_t dst = sbase + (mat << 14) + (uint32_t)(boff ^ ((boff >> 3) & 0x70));
        asm volatile("cp.async.cg.shared.global [%0], [%1], 16;"
                     :: "r"(dst), "l"(src) : "memory");
    }
}

template <bool REMAP_Q, bool HAS_BIAS>
__global__ void __launch_bounds__(256) gemm_hmma(
    const __nv_bfloat16* __restrict__ Ah, const __nv_bfloat16* __restrict__ Al,
    const __nv_bfloat16* __restrict__ Bh, const __nv_bfloat16* __restrict__ Bl,
    const float* __restrict__ bias, float* __restrict__ C, int K)
{
    extern __shared__ __align__(128) char smem[];
    const uint32_t sb = smem_u32(smem);
    const int tid  = threadIdx.x;
    const int wid  = tid >> 5;
    const int lane = tid & 31;
    const int mw   = wid >> 2;          // 0..1
    const int nw   = wid & 3;           // 0..3
    const int n0   = blockIdx.x << 7;
    const int m0   = blockIdx.y << 7;
    const int NCH  = K >> 6;

    // per-thread ldmatrix address components (swizzle mask = (row&7)<<4)
    const int la        = lane & 15;
    const uint32_t rowA = (uint32_t)(mw * 64 + la) * 128;
    const uint32_t mskA = (uint32_t)(la & 7) << 4;
    const uint32_t kA   = (uint32_t)(lane >> 4) << 4;          // 0 or 16 bytes
    const int      rB   = nw * 32 + ((lane >> 4) << 3) + (lane & 7);
    const uint32_t rowB = (uint32_t)rB * 128;
    const uint32_t mskB = (uint32_t)(lane & 7) << 4;
    const uint32_t kB   = (uint32_t)((lane >> 3) & 1) << 4;    // 0 or 16 bytes

    float acc[4][4][4];
#pragma unroll
    for (int i = 0; i < 4; ++i)
#pragma unroll
        for (int j = 0; j < 4; ++j)
#pragma unroll
            for (int v = 0; v < 4; ++v) acc[i][j][v] = 0.f;

    // prologue: fill pipeline
#pragma unroll
    for (int c = 0; c < GEMM_STAGES; ++c) {
        load_tiles(sb + c * STAGE_BYTES, Ah, Al, Bh, Bl, m0, n0, c << 6, K, tid);
        CP_COMMIT();
    }

    int s = 0;
    for (int c = 0; c < NCH; ++c) {
        if (c <= NCH - 3)      CP_WAIT(2);
        else if (c == NCH - 2) CP_WAIT(1);
        else                   CP_WAIT(0);
        __syncthreads();

        const uint32_t bAh = sb + s * STAGE_BYTES;
        const uint32_t bAl = bAh + TILE_BYTES;
        const uint32_t bBh = bAh + 2 * TILE_BYTES;
        const uint32_t bBl = bAh + 3 * TILE_BYTES;

#pragma unroll
        for (int t = 0; t < 4; ++t) {
            const uint32_t kbA = ((uint32_t)(t * 32) + kA) ^ mskA;
            const uint32_t kbB = ((uint32_t)(t * 32) + kB) ^ mskB;

            uint32_t ah[4][4], al[4][4], bh[4][2], bl[4][2];
#pragma unroll
            for (int mi = 0; mi < 4; ++mi) {
                uint32_t off = rowA + (uint32_t)(mi * 2048) + kbA;
                ldsm_x4(bAh + off, ah[mi][0], ah[mi][1], ah[mi][2], ah[mi][3]);
                ldsm_x4(bAl + off, al[mi][0], al[mi][1], al[mi][2], al[mi][3]);
            }
#pragma unroll
            for (int bt = 0; bt < 2; ++bt) {
                uint32_t off = rowB + (uint32_t)(bt * 2048) + kbB;
                ldsm_x4(bBh + off, bh[bt*2][0], bh[bt*2][1],
                                    bh[bt*2+1][0], bh[bt*2+1][1]);
                ldsm_x4(bBl + off, bl[bt*2][0], bl[bt*2][1],
                                    bl[bt*2+1][0], bl[bt*2+1][1]);
            }
#pragma unroll
            for (int mi = 0; mi < 4; ++mi)
#pragma unroll
                for (int ni = 0; ni < 4; ++ni) {
                    mma_bf16(acc[mi][ni], ah[mi], bh[ni]);
                    mma_bf16(acc[mi][ni], ah[mi], bl[ni]);
                    mma_bf16(acc[mi][ni], al[mi], bh[ni]);
                }
        }

        __syncthreads();
        if (c + GEMM_STAGES < NCH) {
            load_tiles(sb + s * STAGE_BYTES, Ah, Al, Bh, Bl,
                       m0, n0, (c + GEMM_STAGES) << 6, K, tid);
            CP_COMMIT();
        }
        s = (s == GEMM_STAGES - 1) ? 0 : s + 1;
    }

    // epilogue: direct register -> global stores (float2 per fragment pair)
#pragma unroll
    for (int mi = 0; mi < 4; ++mi) {
        const int mbase = m0 + mw * 64 + mi * 16 + (lane >> 2);
#pragma unroll
        for (int ni = 0; ni < 4; ++ni) {
            const int n = n0 + nw * 32 + ni * 8 + (lane & 3) * 2;
            float2 v0, v1;
            v0.x = acc[mi][ni][0]; v0.y = acc[mi][ni][1];   // row mbase
            v1.x = acc[mi][ni][2]; v1.y = acc[mi][ni][3];   // row mbase+8
            if (HAS_BIAS) {
                float b0 = bias[n], b1 = bias[n + 1];
                v0.x += b0; v0.y += b1; v1.x += b0; v1.y += b1;
            }
            if (REMAP_Q) {
                const int h = n >> 6, d = n & 63;
                const int b0i = mbase >> 12, s0 = mbase & 4095;
                float* p0 = g_q + (((size_t)(b0i * NH + h) * SQ + s0) * DH + d);
                const int m1 = mbase + 8;
                const int b1i = m1 >> 12, s1 = m1 & 4095;
                float* p1 = g_q + (((size_t)(b1i * NH + h) * SQ + s1) * DH + d);
                *(float2*)p0 = v0;
                *(float2*)p1 = v1;
            } else {
                *(float2*)(C + (size_t)mbase * QD + n) = v0;
                *(float2*)(C + (size_t)(mbase + 8) * QD + n) = v1;
            }
        }
    }
}

// ---------------------------------------------------------------------------
// Two-segment softmax attention (fp32 math; outputs bf16 hi/lo split)
// ---------------------------------------------------------------------------
#define ATTN_SMEM_FLOATS (2 * SCTX * DH + 256 * 97)
#define ATTN_SMEM_BYTES  (ATTN_SMEM_FLOATS * 4)

__global__ void __launch_bounds__(256) attn_kernel(
    const float* __restrict__ scale_p, const int* __restrict__ nimg_p)
{
    extern __shared__ float sm[];
    float* Ks = sm;
    float* Vs = sm + SCTX * DH;
    float* Ls = sm + 2 * SCTX * DH;

    const int tid = threadIdx.x;
    const int bh  = blockIdx.x;
    const int q0  = blockIdx.y << 8;
    const int b   = bh / NH;
    const int h   = bh % NH;
    const int eos = SCTX - *nimg_p;
    const float ipscale = *scale_p;

    const float4* kg = (const float4*)(g_k + (size_t)bh * SCTX * DH);
    const float4* vg = (const float4*)(g_v + (size_t)bh * SCTX * DH);
    float4* K4 = (float4*)Ks;
    float4* V4 = (float4*)Vs;
    for (int i = tid; i < SCTX * DH / 4; i += 256) { K4[i] = kg[i]; V4[i] = vg[i]; }

    const float* qg = g_q + ((size_t)bh * SQ + q0) * DH;
    for (int i = tid; i < 256 * DH; i += 256) {
        int rr = i >> 6, d = i & 63;
        Ls[rr * 65 + d] = qg[i];
    }
    __syncthreads();
    float q[64];
#pragma unroll
    for (int d = 0; d < 64; ++d) q[d] = Ls[tid * 65 + d];
    __syncthreads();

    float* Lrow = Ls + tid * 97;
    for (int s = 0; s < SCTX; ++s) {
        const float4* krow = K4 + s * 16;
        float acc = 0.f;
#pragma unroll
        for (int d4 = 0; d4 < 16; ++d4) {
            float4 kv = krow[d4];
            acc = fmaf(q[d4 * 4 + 0], kv.x, acc);
            acc = fmaf(q[d4 * 4 + 1], kv.y, acc);
            acc = fmaf(q[d4 * 4 + 2], kv.z, acc);
            acc = fmaf(q[d4 * 4 + 3], kv.w, acc);
        }
        Lrow[s] = acc * 0.125f;
    }

    float m1 = -1e30f, m2 = -1e30f;
    for (int s = 0;   s < eos;  ++s) m1 = fmaxf(m1, Lrow[s]);
    for (int s = eos; s < SCTX; ++s) m2 = fmaxf(m2, Lrow[s]);
    float d1 = 0.f, d2 = 0.f;
    for (int s = 0;   s < eos;  ++s) d1 += __expf(Lrow[s] - m1);
    for (int s = eos; s < SCTX; ++s) d2 += __expf(Lrow[s] - m2);
    float w1 = 1.f / d1;
    float w2 = (eos < SCTX && d2 > 0.f) ? (ipscale / d2) : 0.f;

    float o[64];
#pragma unroll
    for (int d = 0; d < 64; ++d) o[d] = 0.f;
    for (int s = 0; s < SCTX; ++s) {
        float l = Lrow[s];
        float w = (s < eos) ? (__expf(l - m1) * w1) : (__expf(l - m2) * w2);
        const float4* vrow = V4 + s * 16;
#pragma unroll
        for (int d4 = 0; d4 < 16; ++d4) {
            float4 vv = vrow[d4];
            o[d4 * 4 + 0] = fmaf(w, vv.x, o[d4 * 4 + 0]);
            o[d4 * 4 + 1] = fmaf(w, vv.y, o[d4 * 4 + 1]);
            o[d4 * 4 + 2] = fmaf(w, vv.z, o[d4 * 4 + 2]);
            o[d4 * 4 + 3] = fmaf(w, vv.w, o[d4 * 4 + 3]);
        }
    }

    __syncthreads();
#pragma unroll
    for (int d = 0; d < 64; ++d) Ls[tid * 65 + d] = o[d];
    __syncthreads();
    __nv_bfloat16* ogh = g_ah + ((size_t)b * SQ + q0) * INNER + h * DH;
    __nv_bfloat16* ogl = g_al + ((size_t)b * SQ + q0) * INNER + h * DH;
    for (int i = tid; i < 256 * DH; i += 256) {
        int rr = i >> 6, d = i & 63;
        float val = Ls[rr * 65 + d];
        __nv_bfloat16 hh = __float2bfloat16(val);
        ogh[(size_t)rr * INNER + d] = hh;
        ogl[(size_t)rr * INNER + d] = __float2bfloat16(val - __bfloat162float(hh));
    }
}

// ---------------------------------------------------------------------------
// Launch: x, context, scale, num_img_token, Wq, Wk, Wv, Wk_ip, Wv_ip, Wout, b_out
// ---------------------------------------------------------------------------
extern "C" void kernel_launch(void* const* d_in, const int* in_sizes, int n_in,
                              void* d_out, int out_size)
{
    const float* x     = (const float*)d_in[0];
    const float* ctx   = (const float*)d_in[1];
    const float* scale = (const float*)d_in[2];
    const int*   nimg  = (const int*)  d_in[3];
    const float* Wq    = (const float*)d_in[4];
    const float* Wk    = (const float*)d_in[5];
    const float* Wv    = (const float*)d_in[6];
    const float* Wki   = (const float*)d_in[7];
    const float* Wvi   = (const float*)d_in[8];
    const float* Wout  = (const float*)d_in[9];
    const float* bout  = (const float*)d_in[10];
    float*       out   = (float*)d_out;

    float *qp;
    __nv_bfloat16 *xh, *xl, *ah, *al, *wqh, *wql, *woh, *wol;
    cudaGetSymbolAddress((void**)&qp,  g_q);
    cudaGetSymbolAddress((void**)&xh,  g_xh);
    cudaGetSymbolAddress((void**)&xl,  g_xl);
    cudaGetSymbolAddress((void**)&ah,  g_ah);
    cudaGetSymbolAddress((void**)&al,  g_al);
    cudaGetSymbolAddress((void**)&wqh, g_wqh);
    cudaGetSymbolAddress((void**)&wql, g_wql);
    cudaGetSymbolAddress((void**)&woh, g_woh);
    cudaGetSymbolAddress((void**)&wol, g_wol);

    cudaFuncSetAttribute(attn_kernel,
        cudaFuncAttributeMaxDynamicSharedMemorySize, ATTN_SMEM_BYTES);
    cudaFuncSetAttribute(gemm_hmma<true, false>,
        cudaFuncAttributeMaxDynamicSharedMemorySize, GEMM_SMEM);
    cudaFuncSetAttribute(gemm_hmma<false, true>,
        cudaFuncAttributeMaxDynamicSharedMemorySize, GEMM_SMEM);

    // conversions
    split_bf16<<<4096, 256>>>((const float4*)x, (ushort4*)xh, (ushort4*)xl,
                              (int)((size_t)BB * SQ * QD / 4));
    split_bf16<<<1600, 256>>>((const float4*)Wq, (ushort4*)wqh, (ushort4*)wql,
                              INNER * QD / 4);
    split_bf16<<<1600, 256>>>((const float4*)Wout, (ushort4*)woh, (ushort4*)wol,
                              QD * INNER / 4);

    // K/V projections
    kv_proj_kernel<<<dim3(NH, BB), 512>>>(ctx, Wk, Wv, Wki, Wvi, nimg);

    // Q projection (HMMA bf16x3), scattered into [b,h,s,d]
    gemm_hmma<true, false><<<dim3(INNER / 128, (BB * SQ) / 128), 256, GEMM_SMEM>>>(
        xh, xl, wqh, wql, nullptr, qp, QD);

    // fused two-segment attention -> bf16 hi/lo
    attn_kernel<<<dim3(BB * NH, SQ / 256), 256, ATTN_SMEM_BYTES>>>(scale, nimg);

    // output projection + bias (HMMA bf16x3)
    gemm_hmma<false, true><<<dim3(QD / 128, (BB * SQ) / 128), 256, GEMM_SMEM>>>(
        ah, al, woh, wol, bout, out, INNER);
}

// round 4
// speedup vs baseline: 1.9211x; 1.0356x over previous
#include <cuda_runtime.h>
#include <cuda_bf16.h>
#include <cstdint>
#include <cstddef>

// Problem constants
#define BB    8
#define SQ    4096
#define QD    1280
#define SCTX  93
#define CD    2048
#define NH    20
#define DH    64
#define INNER 1280

// ---------------------------------------------------------------------------
// Scratch (__device__ globals; no allocs allowed)
// ---------------------------------------------------------------------------
__device__ float         g_q  [(size_t)BB * NH * SQ * DH];   // Q fp32 [b,h,s,d]
__device__ __nv_bfloat16 g_xh [(size_t)BB * SQ * QD];
__device__ __nv_bfloat16 g_xl [(size_t)BB * SQ * QD];
__device__ __nv_bfloat16 g_ah [(size_t)BB * SQ * INNER];
__device__ __nv_bfloat16 g_al [(size_t)BB * SQ * INNER];
__device__ __nv_bfloat16 g_wqh[(size_t)INNER * QD];
__device__ __nv_bfloat16 g_wql[(size_t)INNER * QD];
__device__ __nv_bfloat16 g_woh[(size_t)QD * INNER];
__device__ __nv_bfloat16 g_wol[(size_t)QD * INNER];
__device__ float g_k[(size_t)BB * NH * SCTX * DH];
__device__ float g_v[(size_t)BB * NH * SCTX * DH];

// ---------------------------------------------------------------------------
// Helpers (arch-agnostic PTX only: cp.async, ldmatrix, mma.sync)
// ---------------------------------------------------------------------------
__device__ __forceinline__ uint32_t smem_u32(const void* p) {
    uint32_t a;
    asm("{ .reg .u64 t; cvta.to.shared.u64 t, %1; cvt.u32.u64 %0, t; }"
        : "=r"(a) : "l"(p));
    return a;
}
#define CP_COMMIT() asm volatile("cp.async.commit_group;" ::: "memory")
#define CP_WAIT(n)  asm volatile("cp.async.wait_group %0;" :: "n"(n) : "memory")

__device__ __forceinline__ void ldsm_x4(uint32_t addr, uint32_t& r0, uint32_t& r1,
                                        uint32_t& r2, uint32_t& r3) {
    asm volatile("ldmatrix.sync.aligned.m8n8.x4.shared.b16 {%0,%1,%2,%3}, [%4];"
                 : "=r"(r0), "=r"(r1), "=r"(r2), "=r"(r3) : "r"(addr));
}
__device__ __forceinline__ void mma_bf16(float* c, const uint32_t* a,
                                         const uint32_t* b) {
    asm volatile(
        "mma.sync.aligned.m16n8k16.row.col.f32.bf16.bf16.f32 "
        "{%0,%1,%2,%3}, {%4,%5,%6,%7}, {%8,%9}, {%0,%1,%2,%3};"
        : "+f"(c[0]), "+f"(c[1]), "+f"(c[2]), "+f"(c[3])
        : "r"(a[0]), "r"(a[1]), "r"(a[2]), "r"(a[3]), "r"(b[0]), "r"(b[1]));
}

// ---------------------------------------------------------------------------
// fp32 -> bf16 hi/lo split
// ---------------------------------------------------------------------------
__global__ void split_bf16(const float4* __restrict__ src,
                           ushort4* __restrict__ hi, ushort4* __restrict__ lo,
                           int n4)
{
    for (int i = blockIdx.x * blockDim.x + threadIdx.x; i < n4;
         i += gridDim.x * blockDim.x) {
        float4 v = src[i];
        __nv_bfloat16 h0 = __float2bfloat16(v.x), h1 = __float2bfloat16(v.y);
        __nv_bfloat16 h2 = __float2bfloat16(v.z), h3 = __float2bfloat16(v.w);
        ushort4 H, L;
        H.x = __bfloat16_as_ushort(h0); H.y = __bfloat16_as_ushort(h1);
        H.z = __bfloat16_as_ushort(h2); H.w = __bfloat16_as_ushort(h3);
        L.x = __bfloat16_as_ushort(__float2bfloat16(v.x - __bfloat162float(h0)));
        L.y = __bfloat16_as_ushort(__float2bfloat16(v.y - __bfloat162float(h1)));
        L.z = __bfloat16_as_ushort(__float2bfloat16(v.z - __bfloat162float(h2)));
        L.w = __bfloat16_as_ushort(__float2bfloat16(v.w - __bfloat162float(h3)));
        hi[i] = H; lo[i] = L;
    }
}

// ---------------------------------------------------------------------------
// KV projections (fp32, small)
// ---------------------------------------------------------------------------
__global__ void __launch_bounds__(512) kv_proj_kernel(
    const float* __restrict__ ctx,
    const float* __restrict__ Wk,  const float* __restrict__ Wv,
    const float* __restrict__ Wki, const float* __restrict__ Wvi,
    const int*   __restrict__ nimg_p)
{
    __shared__ float cs[96][17];
    __shared__ float wk_s[64][17], wv_s[64][17], wki_s[64][17], wvi_s[64][17];

    const int tid = threadIdx.x;
    const int b   = blockIdx.y;
    const int hh  = blockIdx.x;
    const int n0  = hh * 64;
    const int eos = SCTX - *nimg_p;
    const int n   = tid & 63;
    const int g   = tid >> 6;

    float ak[12], av[12];
#pragma unroll
    for (int j = 0; j < 12; ++j) { ak[j] = 0.f; av[j] = 0.f; }

    for (int k0 = 0; k0 < CD; k0 += 16) {
        __syncthreads();
        for (int i = tid; i < 96 * 16; i += 512) {
            int s = i >> 4, kk = i & 15;
            cs[s][kk] = (s < SCTX) ? ctx[((size_t)b * SCTX + s) * CD + k0 + kk] : 0.f;
        }
        for (int i = tid; i < 64 * 16; i += 512) {
            int r = i >> 4, kk = i & 15;
            size_t gi = (size_t)(n0 + r) * CD + k0 + kk;
            wk_s [r][kk] = Wk [gi]; wv_s [r][kk] = Wv [gi];
            wki_s[r][kk] = Wki[gi]; wvi_s[r][kk] = Wvi[gi];
        }
        __syncthreads();
#pragma unroll
        for (int kk = 0; kk < 16; ++kk) {
            float wkv = wk_s[n][kk],  wvv = wv_s[n][kk];
            float wkiv = wki_s[n][kk], wviv = wvi_s[n][kk];
#pragma unroll
            for (int j = 0; j < 12; ++j) {
                int s = g * 12 + j;
                float c = cs[s][kk];
                bool txt = (s < eos);
                ak[j] = fmaf(c, txt ? wkv : wkiv, ak[j]);
                av[j] = fmaf(c, txt ? wvv : wviv, av[j]);
            }
        }
    }
    size_t base = ((size_t)(b * NH + hh) * SCTX) * DH + n;
#pragma unroll
    for (int j = 0; j < 12; ++j) {
        int s = g * 12 + j;
        if (s < SCTX) {
            g_k[base + (size_t)s * DH] = ak[j];
            g_v[base + (size_t)s * DH] = av[j];
        }
    }
}

// ---------------------------------------------------------------------------
// HMMA bf16x3 GEMM: C[m,n] = sum_k A[m,k]*B[n,k], A=Ah+Al, B=Bh+Bl.
// 128x128 CTA tile, 8 warps (2m x 4n), 64x32 warp tile, K-chunk 32,
// 3-stage cp.async pipeline, 96KB smem -> 2 CTAs/SM.
// Stage layout: 4 matrices x [128 rows x 64B], SW64-style swizzle:
//   byte16-col perm = cb ^ ((row>>1)&3)   (conflict-free for cp.async+ldmatrix)
// ---------------------------------------------------------------------------
#define GEMM_STAGES 3
#define TILE_BYTES  8192                  // one 128x32 bf16 tile
#define STAGE_BYTES (4 * TILE_BYTES)      // Ah, Al, Bh, Bl
#define GEMM_SMEM   (GEMM_STAGES * STAGE_BYTES)

__device__ __forceinline__ void load_tiles(
    uint32_t sbase,
    const __nv_bfloat16* __restrict__ Ah, const __nv_bfloat16* __restrict__ Al,
    const __nv_bfloat16* __restrict__ Bh, const __nv_bfloat16* __restrict__ Bl,
    int m0, int n0, int k0, int K, int tid)
{
#pragma unroll
    for (int i = 0; i < 8; ++i) {
        int idx = tid + (i << 8);            // 0..2047 16B chunks
        int mat = idx >> 9;                  // 0:Ah 1:Al 2:Bh 3:Bl
        int w   = idx & 511;
        int r   = w >> 2;                    // 0..127
        int cb  = w & 3;                     // 16B column
        int grow = ((mat < 2) ? m0 : n0) + r;
        const __nv_bfloat16* base = (mat == 0) ? Ah : (mat == 1) ? Al
                                  : (mat == 2) ? Bh : Bl;
        const char* src = (const char*)(base + (size_t)grow * K + k0) + (cb << 4);
        uint32_t dst = sbase + (mat << 13) + (r << 6)
                     + (uint32_t)((cb ^ ((r >> 1) & 3)) << 4);
        asm volatile("cp.async.cg.shared.global [%0], [%1], 16;"
                     :: "r"(dst), "l"(src) : "memory");
    }
}

template <bool REMAP_Q, bool HAS_BIAS>
__global__ void __launch_bounds__(256, 2) gemm_hmma(
    const __nv_bfloat16* __restrict__ Ah, const __nv_bfloat16* __restrict__ Al,
    const __nv_bfloat16* __restrict__ Bh, const __nv_bfloat16* __restrict__ Bl,
    const float* __restrict__ bias, float* __restrict__ C, int K)
{
    extern __shared__ __align__(128) char smem[];
    const uint32_t sb = smem_u32(smem);
    const int tid  = threadIdx.x;
    const int wid  = tid >> 5;
    const int lane = tid & 31;
    const int mw   = wid >> 2;          // 0..1
    const int nw   = wid & 3;           // 0..3
    const int n0   = blockIdx.x << 7;
    const int m0   = blockIdx.y << 7;
    const int NCH  = K >> 5;

    // per-thread fragment address components
    uint32_t aoff[4], axor[4];
#pragma unroll
    for (int mi = 0; mi < 4; ++mi) {
        uint32_t rA = (uint32_t)(mw * 64 + mi * 16 + (lane & 15));
        aoff[mi] = rA << 6;
        axor[mi] = (rA >> 1) & 3;
    }
    uint32_t boff[2], bxor[2];
#pragma unroll
    for (int bt = 0; bt < 2; ++bt) {
        uint32_t rB = (uint32_t)(nw * 32 + bt * 16 + ((lane >> 4) << 3)
                                 + (lane & 7));
        boff[bt] = rB << 6;
        bxor[bt] = (rB >> 1) & 3;
    }
    const uint32_t cA = (uint32_t)(lane >> 4);        // 0/1
    const uint32_t cB = (uint32_t)((lane >> 3) & 1);  // 0/1

    float acc[4][4][4];
#pragma unroll
    for (int i = 0; i < 4; ++i)
#pragma unroll
        for (int j = 0; j < 4; ++j)
#pragma unroll
            for (int v = 0; v < 4; ++v) acc[i][j][v] = 0.f;

    // prologue: fill S-1 = 2 stages
#pragma unroll
    for (int c = 0; c < GEMM_STAGES - 1; ++c) {
        load_tiles(sb + c * STAGE_BYTES, Ah, Al, Bh, Bl, m0, n0, c << 5, K, tid);
        CP_COMMIT();
    }

    int s = 0;
    for (int c = 0; c < NCH; ++c) {
        CP_WAIT(1);
        __syncthreads();

        // prefetch chunk c+2 into stage (c+2)%3 (= the stage freed by c-1)
        if (c + GEMM_STAGES - 1 < NCH) {
            int sn = c + GEMM_STAGES - 1;
            load_tiles(sb + (sn % GEMM_STAGES) * STAGE_BYTES, Ah, Al, Bh, Bl,
                       m0, n0, sn << 5, K, tid);
        }
        CP_COMMIT();

        const uint32_t bAh = sb + s * STAGE_BYTES;
        const uint32_t bAl = bAh + TILE_BYTES;
        const uint32_t bBh = bAh + 2 * TILE_BYTES;
        const uint32_t bBl = bAh + 3 * TILE_BYTES;

#pragma unroll
        for (int t = 0; t < 2; ++t) {
            const uint32_t cbA = (uint32_t)(2 * t) + cA;
            const uint32_t cbB = (uint32_t)(2 * t) + cB;

            uint32_t ah[4][4], al[4][4], bh[4][2], bl[4][2];
#pragma unroll
            for (int mi = 0; mi < 4; ++mi) {
                uint32_t off = aoff[mi] + ((cbA ^ axor[mi]) << 4);
                ldsm_x4(bAh + off, ah[mi][0], ah[mi][1], ah[mi][2], ah[mi][3]);
                ldsm_x4(bAl + off, al[mi][0], al[mi][1], al[mi][2], al[mi][3]);
            }
#pragma unroll
            for (int bt = 0; bt < 2; ++bt) {
                uint32_t off = boff[bt] + ((cbB ^ bxor[bt]) << 4);
                ldsm_x4(bBh + off, bh[bt*2][0], bh[bt*2][1],
                                    bh[bt*2+1][0], bh[bt*2+1][1]);
                ldsm_x4(bBl + off, bl[bt*2][0], bl[bt*2][1],
                                    bl[bt*2+1][0], bl[bt*2+1][1]);
            }
#pragma unroll
            for (int mi = 0; mi < 4; ++mi)
#pragma unroll
                for (int ni = 0; ni < 4; ++ni) {
                    mma_bf16(acc[mi][ni], ah[mi], bh[ni]);
                    mma_bf16(acc[mi][ni], ah[mi], bl[ni]);
                    mma_bf16(acc[mi][ni], al[mi], bh[ni]);
                }
        }
        s = (s == GEMM_STAGES - 1) ? 0 : s + 1;
    }

    // epilogue: direct register -> global stores
#pragma unroll
    for (int mi = 0; mi < 4; ++mi) {
        const int mbase = m0 + mw * 64 + mi * 16 + (lane >> 2);
#pragma unroll
        for (int ni = 0; ni < 4; ++ni) {
            const int n = n0 + nw * 32 + ni * 8 + (lane & 3) * 2;
            float2 v0, v1;
            v0.x = acc[mi][ni][0]; v0.y = acc[mi][ni][1];
            v1.x = acc[mi][ni][2]; v1.y = acc[mi][ni][3];
            if (HAS_BIAS) {
                float b0 = bias[n], b1 = bias[n + 1];
                v0.x += b0; v0.y += b1; v1.x += b0; v1.y += b1;
            }
            if (REMAP_Q) {
                const int h = n >> 6, d = n & 63;
                const int b0i = mbase >> 12, s0 = mbase & 4095;
                float* p0 = g_q + (((size_t)(b0i * NH + h) * SQ + s0) * DH + d);
                const int m1 = mbase + 8;
                const int b1i = m1 >> 12, s1 = m1 & 4095;
                float* p1 = g_q + (((size_t)(b1i * NH + h) * SQ + s1) * DH + d);
                *(float2*)p0 = v0;
                *(float2*)p1 = v1;
            } else {
                *(float2*)(C + (size_t)mbase * QD + n) = v0;
                *(float2*)(C + (size_t)(mbase + 8) * QD + n) = v1;
            }
        }
    }
}

// ---------------------------------------------------------------------------
// Two-segment softmax attention (fp32 math; outputs bf16 hi/lo split)
// ---------------------------------------------------------------------------
#define ATTN_SMEM_FLOATS (2 * SCTX * DH + 256 * 97)
#define ATTN_SMEM_BYTES  (ATTN_SMEM_FLOATS * 4)

__global__ void __launch_bounds__(256) attn_kernel(
    const float* __restrict__ scale_p, const int* __restrict__ nimg_p)
{
    extern __shared__ float sm[];
    float* Ks = sm;
    float* Vs = sm + SCTX * DH;
    float* Ls = sm + 2 * SCTX * DH;

    const int tid = threadIdx.x;
    const int bh  = blockIdx.x;
    const int q0  = blockIdx.y << 8;
    const int b   = bh / NH;
    const int h   = bh % NH;
    const int eos = SCTX - *nimg_p;
    const float ipscale = *scale_p;

    const float4* kg = (const float4*)(g_k + (size_t)bh * SCTX * DH);
    const float4* vg = (const float4*)(g_v + (size_t)bh * SCTX * DH);
    float4* K4 = (float4*)Ks;
    float4* V4 = (float4*)Vs;
    for (int i = tid; i < SCTX * DH / 4; i += 256) { K4[i] = kg[i]; V4[i] = vg[i]; }

    const float* qg = g_q + ((size_t)bh * SQ + q0) * DH;
    for (int i = tid; i < 256 * DH; i += 256) {
        int rr = i >> 6, d = i & 63;
        Ls[rr * 65 + d] = qg[i];
    }
    __syncthreads();
    float q[64];
#pragma unroll
    for (int d = 0; d < 64; ++d) q[d] = Ls[tid * 65 + d];
    __syncthreads();

    float* Lrow = Ls + tid * 97;
    for (int s = 0; s < SCTX; ++s) {
        const float4* krow = K4 + s * 16;
        float acc = 0.f;
#pragma unroll
        for (int d4 = 0; d4 < 16; ++d4) {
            float4 kv = krow[d4];
            acc = fmaf(q[d4 * 4 + 0], kv.x, acc);
            acc = fmaf(q[d4 * 4 + 1], kv.y, acc);
            acc = fmaf(q[d4 * 4 + 2], kv.z, acc);
            acc = fmaf(q[d4 * 4 + 3], kv.w, acc);
        }
        Lrow[s] = acc * 0.125f;
    }

    float m1 = -1e30f, m2 = -1e30f;
    for (int s = 0;   s < eos;  ++s) m1 = fmaxf(m1, Lrow[s]);
    for (int s = eos; s < SCTX; ++s) m2 = fmaxf(m2, Lrow[s]);
    float d1 = 0.f, d2 = 0.f;
    for (int s = 0;   s < eos;  ++s) d1 += __expf(Lrow[s] - m1);
    for (int s = eos; s < SCTX; ++s) d2 += __expf(Lrow[s] - m2);
    float w1 = 1.f / d1;
    float w2 = (eos < SCTX && d2 > 0.f) ? (ipscale / d2) : 0.f;

    float o[64];
#pragma unroll
    for (int d = 0; d < 64; ++d) o[d] = 0.f;
    for (int s = 0; s < SCTX; ++s) {
        float l = Lrow[s];
        float w = (s < eos) ? (__expf(l - m1) * w1) : (__expf(l - m2) * w2);
        const float4* vrow = V4 + s * 16;
#pragma unroll
        for (int d4 = 0; d4 < 16; ++d4) {
            float4 vv = vrow[d4];
            o[d4 * 4 + 0] = fmaf(w, vv.x, o[d4 * 4 + 0]);
            o[d4 * 4 + 1] = fmaf(w, vv.y, o[d4 * 4 + 1]);
            o[d4 * 4 + 2] = fmaf(w, vv.z, o[d4 * 4 + 2]);
            o[d4 * 4 + 3] = fmaf(w, vv.w, o[d4 * 4 + 3]);
        }
    }

    __syncthreads();
#pragma unroll
    for (int d = 0; d < 64; ++d) Ls[tid * 65 + d] = o[d];
    __syncthreads();
    __nv_bfloat16* ogh = g_ah + ((size_t)b * SQ + q0) * INNER + h * DH;
    __nv_bfloat16* ogl = g_al + ((size_t)b * SQ + q0) * INNER + h * DH;
    for (int i = tid; i < 256 * DH; i += 256) {
        int rr = i >> 6, d = i & 63;
        float val = Ls[rr * 65 + d];
        __nv_bfloat16 hh = __float2bfloat16(val);
        ogh[(size_t)rr * INNER + d] = hh;
        ogl[(size_t)rr * INNER + d] = __float2bfloat16(val - __bfloat162float(hh));
    }
}

// ---------------------------------------------------------------------------
// Launch: x, context, scale, num_img_token, Wq, Wk, Wv, Wk_ip, Wv_ip, Wout, b_out
// ---------------------------------------------------------------------------
extern "C" void kernel_launch(void* const* d_in, const int* in_sizes, int n_in,
                              void* d_out, int out_size)
{
    const float* x     = (const float*)d_in[0];
    const float* ctx   = (const float*)d_in[1];
    const float* scale = (const float*)d_in[2];
    const int*   nimg  = (const int*)  d_in[3];
    const float* Wq    = (const float*)d_in[4];
    const float* Wk    = (const float*)d_in[5];
    const float* Wv    = (const float*)d_in[6];
    const float* Wki   = (const float*)d_in[7];
    const float* Wvi   = (const float*)d_in[8];
    const float* Wout  = (const float*)d_in[9];
    const float* bout  = (const float*)d_in[10];
    float*       out   = (float*)d_out;

    float *qp;
    __nv_bfloat16 *xh, *xl, *ah, *al, *wqh, *wql, *woh, *wol;
    cudaGetSymbolAddress((void**)&qp,  g_q);
    cudaGetSymbolAddress((void**)&xh,  g_xh);
    cudaGetSymbolAddress((void**)&xl,  g_xl);
    cudaGetSymbolAddress((void**)&ah,  g_ah);
    cudaGetSymbolAddress((void**)&al,  g_al);
    cudaGetSymbolAddress((void**)&wqh, g_wqh);
    cudaGetSymbolAddress((void**)&wql, g_wql);
    cudaGetSymbolAddress((void**)&woh, g_woh);
    cudaGetSymbolAddress((void**)&wol, g_wol);

    cudaFuncSetAttribute(attn_kernel,
        cudaFuncAttributeMaxDynamicSharedMemorySize, ATTN_SMEM_BYTES);
    cudaFuncSetAttribute(gemm_hmma<true, false>,
        cudaFuncAttributeMaxDynamicSharedMemorySize, GEMM_SMEM);
    cudaFuncSetAttribute(gemm_hmma<false, true>,
        cudaFuncAttributeMaxDynamicSharedMemorySize, GEMM_SMEM);

    // conversions
    split_bf16<<<4096, 256>>>((const float4*)x, (ushort4*)xh, (ushort4*)xl,
                              (int)((size_t)BB * SQ * QD / 4));
    split_bf16<<<1600, 256>>>((const float4*)Wq, (ushort4*)wqh, (ushort4*)wql,
                              INNER * QD / 4);
    split_bf16<<<1600, 256>>>((const float4*)Wout, (ushort4*)woh, (ushort4*)wol,
                              QD * INNER / 4);

    // K/V projections
    kv_proj_kernel<<<dim3(NH, BB), 512>>>(ctx, Wk, Wv, Wki, Wvi, nimg);

    // Q projection (HMMA bf16x3), scattered into [b,h,s,d]
    gemm_hmma<true, false><<<dim3(INNER / 128, (BB * SQ) / 128), 256, GEMM_SMEM>>>(
        xh, xl, wqh, wql, nullptr, qp, QD);

    // fused two-segment attention -> bf16 hi/lo
    attn_kernel<<<dim3(BB * NH, SQ / 256), 256, ATTN_SMEM_BYTES>>>(scale, nimg);

    // output projection + bias (HMMA bf16x3)
    gemm_hmma<false, true><<<dim3(QD / 128, (BB * SQ) / 128), 256, GEMM_SMEM>>>(
        ah, al, woh, wol, bout, out, INNER);
}

// round 5
// speedup vs baseline: 2.4319x; 1.2659x over previous
#include <cuda_runtime.h>
#include <cuda_bf16.h>
#include <cstdint>
#include <cstddef>

// Problem constants
#define BB    8
#define SQ    4096
#define QD    1280
#define SCTX  93
#define CD    2048
#define NH    20
#define DH    64
#define INNER 1280

// ---------------------------------------------------------------------------
// Scratch (__device__ globals; no allocs allowed)
// ---------------------------------------------------------------------------
__device__ float         g_q  [(size_t)BB * NH * SQ * DH];   // Q fp32 [b,h,s,d]
__device__ __nv_bfloat16 g_xh [(size_t)BB * SQ * QD];
__device__ __nv_bfloat16 g_xl [(size_t)BB * SQ * QD];
__device__ __nv_bfloat16 g_ah [(size_t)BB * SQ * INNER];
__device__ __nv_bfloat16 g_al [(size_t)BB * SQ * INNER];
__device__ __nv_bfloat16 g_wqh[(size_t)INNER * QD];
__device__ __nv_bfloat16 g_wql[(size_t)INNER * QD];
__device__ __nv_bfloat16 g_woh[(size_t)QD * INNER];
__device__ __nv_bfloat16 g_wol[(size_t)QD * INNER];
__device__ float g_k[(size_t)BB * NH * SCTX * DH];
__device__ float g_v[(size_t)BB * NH * SCTX * DH];

// ---------------------------------------------------------------------------
// Helpers (arch-agnostic PTX only: cp.async, ldmatrix, mma.sync)
// ---------------------------------------------------------------------------
__device__ __forceinline__ uint32_t smem_u32(const void* p) {
    uint32_t a;
    asm("{ .reg .u64 t; cvta.to.shared.u64 t, %1; cvt.u32.u64 %0, t; }"
        : "=r"(a) : "l"(p));
    return a;
}
#define CP_COMMIT() asm volatile("cp.async.commit_group;" ::: "memory")
#define CP_WAIT(n)  asm volatile("cp.async.wait_group %0;" :: "n"(n) : "memory")

__device__ __forceinline__ void ldsm_x4(uint32_t addr, uint32_t& r0, uint32_t& r1,
                                        uint32_t& r2, uint32_t& r3) {
    asm volatile("ldmatrix.sync.aligned.m8n8.x4.shared.b16 {%0,%1,%2,%3}, [%4];"
                 : "=r"(r0), "=r"(r1), "=r"(r2), "=r"(r3) : "r"(addr));
}
__device__ __forceinline__ void mma_bf16(float* c, const uint32_t* a,
                                         const uint32_t* b) {
    asm volatile(
        "mma.sync.aligned.m16n8k16.row.col.f32.bf16.bf16.f32 "
        "{%0,%1,%2,%3}, {%4,%5,%6,%7}, {%8,%9}, {%0,%1,%2,%3};"
        : "+f"(c[0]), "+f"(c[1]), "+f"(c[2]), "+f"(c[3])
        : "r"(a[0]), "r"(a[1]), "r"(a[2]), "r"(a[3]), "r"(b[0]), "r"(b[1]));
}
__device__ __forceinline__ uint32_t packbf(float x, float y) {
    __nv_bfloat162 t = __floats2bfloat162_rn(x, y);   // .x = x (low half)
    return *(uint32_t*)&t;
}
__device__ __forceinline__ float bfres(float x) {     // residual after bf16 round
    return x - __bfloat162float(__float2bfloat16(x));
}

// ---------------------------------------------------------------------------
// fp32 -> bf16 hi/lo split
// ---------------------------------------------------------------------------
__global__ void split_bf16(const float4* __restrict__ src,
                           ushort4* __restrict__ hi, ushort4* __restrict__ lo,
                           int n4)
{
    for (int i = blockIdx.x * blockDim.x + threadIdx.x; i < n4;
         i += gridDim.x * blockDim.x) {
        float4 v = src[i];
        __nv_bfloat16 h0 = __float2bfloat16(v.x), h1 = __float2bfloat16(v.y);
        __nv_bfloat16 h2 = __float2bfloat16(v.z), h3 = __float2bfloat16(v.w);
        ushort4 H, L;
        H.x = __bfloat16_as_ushort(h0); H.y = __bfloat16_as_ushort(h1);
        H.z = __bfloat16_as_ushort(h2); H.w = __bfloat16_as_ushort(h3);
        L.x = __bfloat16_as_ushort(__float2bfloat16(v.x - __bfloat162float(h0)));
        L.y = __bfloat16_as_ushort(__float2bfloat16(v.y - __bfloat162float(h1)));
        L.z = __bfloat16_as_ushort(__float2bfloat16(v.z - __bfloat162float(h2)));
        L.w = __bfloat16_as_ushort(__float2bfloat16(v.w - __bfloat162float(h3)));
        hi[i] = H; lo[i] = L;
    }
}

// ---------------------------------------------------------------------------
// KV projections (fp32, small)
// ---------------------------------------------------------------------------
__global__ void __launch_bounds__(512) kv_proj_kernel(
    const float* __restrict__ ctx,
    const float* __restrict__ Wk,  const float* __restrict__ Wv,
    const float* __restrict__ Wki, const float* __restrict__ Wvi,
    const int*   __restrict__ nimg_p)
{
    __shared__ float cs[96][17];
    __shared__ float wk_s[64][17], wv_s[64][17], wki_s[64][17], wvi_s[64][17];

    const int tid = threadIdx.x;
    const int b   = blockIdx.y;
    const int hh  = blockIdx.x;
    const int n0  = hh * 64;
    const int eos = SCTX - *nimg_p;
    const int n   = tid & 63;
    const int g   = tid >> 6;

    float ak[12], av[12];
#pragma unroll
    for (int j = 0; j < 12; ++j) { ak[j] = 0.f; av[j] = 0.f; }

    for (int k0 = 0; k0 < CD; k0 += 16) {
        __syncthreads();
        for (int i = tid; i < 96 * 16; i += 512) {
            int s = i >> 4, kk = i & 15;
            cs[s][kk] = (s < SCTX) ? ctx[((size_t)b * SCTX + s) * CD + k0 + kk] : 0.f;
        }
        for (int i = tid; i < 64 * 16; i += 512) {
            int r = i >> 4, kk = i & 15;
            size_t gi = (size_t)(n0 + r) * CD + k0 + kk;
            wk_s [r][kk] = Wk [gi]; wv_s [r][kk] = Wv [gi];
            wki_s[r][kk] = Wki[gi]; wvi_s[r][kk] = Wvi[gi];
        }
        __syncthreads();
#pragma unroll
        for (int kk = 0; kk < 16; ++kk) {
            float wkv = wk_s[n][kk],  wvv = wv_s[n][kk];
            float wkiv = wki_s[n][kk], wviv = wvi_s[n][kk];
#pragma unroll
            for (int j = 0; j < 12; ++j) {
                int s = g * 12 + j;
                float c = cs[s][kk];
                bool txt = (s < eos);
                ak[j] = fmaf(c, txt ? wkv : wkiv, ak[j]);
                av[j] = fmaf(c, txt ? wvv : wviv, av[j]);
            }
        }
    }
    size_t base = ((size_t)(b * NH + hh) * SCTX) * DH + n;
#pragma unroll
    for (int j = 0; j < 12; ++j) {
        int s = g * 12 + j;
        if (s < SCTX) {
            g_k[base + (size_t)s * DH] = ak[j];
            g_v[base + (size_t)s * DH] = av[j];
        }
    }
}

// ---------------------------------------------------------------------------
// HMMA bf16x3 GEMM (unchanged from R4): 128x128 tile, K-chunk 32, 3 stages.
// ---------------------------------------------------------------------------
#define GEMM_STAGES 3
#define TILE_BYTES  8192
#define STAGE_BYTES (4 * TILE_BYTES)
#define GEMM_SMEM   (GEMM_STAGES * STAGE_BYTES)

__device__ __forceinline__ void load_tiles(
    uint32_t sbase,
    const __nv_bfloat16* __restrict__ Ah, const __nv_bfloat16* __restrict__ Al,
    const __nv_bfloat16* __restrict__ Bh, const __nv_bfloat16* __restrict__ Bl,
    int m0, int n0, int k0, int K, int tid)
{
#pragma unroll
    for (int i = 0; i < 8; ++i) {
        int idx = tid + (i << 8);
        int mat = idx >> 9;
        int w   = idx & 511;
        int r   = w >> 2;
        int cb  = w & 3;
        int grow = ((mat < 2) ? m0 : n0) + r;
        const __nv_bfloat16* base = (mat == 0) ? Ah : (mat == 1) ? Al
                                  : (mat == 2) ? Bh : Bl;
        const char* src = (const char*)(base + (size_t)grow * K + k0) + (cb << 4);
        uint32_t dst = sbase + (mat << 13) + (r << 6)
                     + (uint32_t)((cb ^ ((r >> 1) & 3)) << 4);
        asm volatile("cp.async.cg.shared.global [%0], [%1], 16;"
                     :: "r"(dst), "l"(src) : "memory");
    }
}

template <bool REMAP_Q, bool HAS_BIAS>
__global__ void __launch_bounds__(256, 2) gemm_hmma(
    const __nv_bfloat16* __restrict__ Ah, const __nv_bfloat16* __restrict__ Al,
    const __nv_bfloat16* __restrict__ Bh, const __nv_bfloat16* __restrict__ Bl,
    const float* __restrict__ bias, float* __restrict__ C, int K)
{
    extern __shared__ __align__(128) char smem[];
    const uint32_t sb = smem_u32(smem);
    const int tid  = threadIdx.x;
    const int wid  = tid >> 5;
    const int lane = tid & 31;
    const int mw   = wid >> 2;
    const int nw   = wid & 3;
    const int n0   = blockIdx.x << 7;
    const int m0   = blockIdx.y << 7;
    const int NCH  = K >> 5;

    uint32_t aoff[4], axor[4];
#pragma unroll
    for (int mi = 0; mi < 4; ++mi) {
        uint32_t rA = (uint32_t)(mw * 64 + mi * 16 + (lane & 15));
        aoff[mi] = rA << 6;
        axor[mi] = (rA >> 1) & 3;
    }
    uint32_t boff[2], bxor[2];
#pragma unroll
    for (int bt = 0; bt < 2; ++bt) {
        uint32_t rB = (uint32_t)(nw * 32 + bt * 16 + ((lane >> 4) << 3)
                                 + (lane & 7));
        boff[bt] = rB << 6;
        bxor[bt] = (rB >> 1) & 3;
    }
    const uint32_t cA = (uint32_t)(lane >> 4);
    const uint32_t cB = (uint32_t)((lane >> 3) & 1);

    float acc[4][4][4];
#pragma unroll
    for (int i = 0; i < 4; ++i)
#pragma unroll
        for (int j = 0; j < 4; ++j)
#pragma unroll
            for (int v = 0; v < 4; ++v) acc[i][j][v] = 0.f;

#pragma unroll
    for (int c = 0; c < GEMM_STAGES - 1; ++c) {
        load_tiles(sb + c * STAGE_BYTES, Ah, Al, Bh, Bl, m0, n0, c << 5, K, tid);
        CP_COMMIT();
    }

    int s = 0;
    for (int c = 0; c < NCH; ++c) {
        CP_WAIT(1);
        __syncthreads();

        if (c + GEMM_STAGES - 1 < NCH) {
            int sn = c + GEMM_STAGES - 1;
            load_tiles(sb + (sn % GEMM_STAGES) * STAGE_BYTES, Ah, Al, Bh, Bl,
                       m0, n0, sn << 5, K, tid);
        }
        CP_COMMIT();

        const uint32_t bAh = sb + s * STAGE_BYTES;
        const uint32_t bAl = bAh + TILE_BYTES;
        const uint32_t bBh = bAh + 2 * TILE_BYTES;
        const uint32_t bBl = bAh + 3 * TILE_BYTES;

#pragma unroll
        for (int t = 0; t < 2; ++t) {
            const uint32_t cbA = (uint32_t)(2 * t) + cA;
            const uint32_t cbB = (uint32_t)(2 * t) + cB;

            uint32_t ah[4][4], al[4][4], bh[4][2], bl[4][2];
#pragma unroll
            for (int mi = 0; mi < 4; ++mi) {
                uint32_t off = aoff[mi] + ((cbA ^ axor[mi]) << 4);
                ldsm_x4(bAh + off, ah[mi][0], ah[mi][1], ah[mi][2], ah[mi][3]);
                ldsm_x4(bAl + off, al[mi][0], al[mi][1], al[mi][2], al[mi][3]);
            }
#pragma unroll
            for (int bt = 0; bt < 2; ++bt) {
                uint32_t off = boff[bt] + ((cbB ^ bxor[bt]) << 4);
                ldsm_x4(bBh + off, bh[bt*2][0], bh[bt*2][1],
                                    bh[bt*2+1][0], bh[bt*2+1][1]);
                ldsm_x4(bBl + off, bl[bt*2][0], bl[bt*2][1],
                                    bl[bt*2+1][0], bl[bt*2+1][1]);
            }
#pragma unroll
            for (int mi = 0; mi < 4; ++mi)
#pragma unroll
                for (int ni = 0; ni < 4; ++ni) {
                    mma_bf16(acc[mi][ni], ah[mi], bh[ni]);
                    mma_bf16(acc[mi][ni], ah[mi], bl[ni]);
                    mma_bf16(acc[mi][ni], al[mi], bh[ni]);
                }
        }
        s = (s == GEMM_STAGES - 1) ? 0 : s + 1;
    }

#pragma unroll
    for (int mi = 0; mi < 4; ++mi) {
        const int mbase = m0 + mw * 64 + mi * 16 + (lane >> 2);
#pragma unroll
        for (int ni = 0; ni < 4; ++ni) {
            const int n = n0 + nw * 32 + ni * 8 + (lane & 3) * 2;
            float2 v0, v1;
            v0.x = acc[mi][ni][0]; v0.y = acc[mi][ni][1];
            v1.x = acc[mi][ni][2]; v1.y = acc[mi][ni][3];
            if (HAS_BIAS) {
                float b0 = bias[n], b1 = bias[n + 1];
                v0.x += b0; v0.y += b1; v1.x += b0; v1.y += b1;
            }
            if (REMAP_Q) {
                const int h = n >> 6, d = n & 63;
                const int b0i = mbase >> 12, s0 = mbase & 4095;
                float* p0 = g_q + (((size_t)(b0i * NH + h) * SQ + s0) * DH + d);
                const int m1 = mbase + 8;
                const int b1i = m1 >> 12, s1 = m1 & 4095;
                float* p1 = g_q + (((size_t)(b1i * NH + h) * SQ + s1) * DH + d);
                *(float2*)p0 = v0;
                *(float2*)p1 = v1;
            } else {
                *(float2*)(C + (size_t)mbase * QD + n) = v0;
                *(float2*)(C + (size_t)(mbase + 8) * QD + n) = v1;
            }
        }
    }
}

// ---------------------------------------------------------------------------
// HMMA flash-style two-segment attention.
// Block = 128 threads (4 warps), handles (bh, 128 q-rows).
// Q/K: bf16 hi/lo swizzled smem tiles (128B rows). V: transposed Vt[d][s],
// 208B row stride (conflict-free ldmatrix). QK^T and P*V in bf16x3 HMMA;
// softmax on fp32 fragments with shfl row-reductions; out -> bf16 hi/lo.
// ---------------------------------------------------------------------------
#define AQH  0
#define AQL  16384
#define AKH  32768
#define AKL  45056
#define AVH  57344
#define AVL  70656
#define ATTN_SMEM 83968     // 64*208*2 + 96*128*2 + 128*128*2

__global__ void __launch_bounds__(128) attn_mma(
    const float* __restrict__ scale_p, const int* __restrict__ nimg_p)
{
    extern __shared__ __align__(128) char smem[];
    const uint32_t sb = smem_u32(smem);
    const int tid  = threadIdx.x;
    const int lane = tid & 31;
    const int w    = tid >> 5;            // warp 0..3 -> q rows w*32..+31
    const int bh   = blockIdx.x;
    const int q0   = blockIdx.y << 7;
    const int b    = bh / NH;
    const int h    = bh % NH;
    const int eos  = SCTX - *nimg_p;
    const float ipscale = *scale_p;

    // ---- build Q tiles (each thread converts one q-row) ----
    {
        const float4* src = (const float4*)(g_q + ((size_t)bh * SQ + q0 + tid) * DH);
#pragma unroll
        for (int cb = 0; cb < 8; ++cb) {
            float4 u = src[cb * 2], v = src[cb * 2 + 1];
            uint4 H, L;
            H.x = packbf(u.x, u.y); H.y = packbf(u.z, u.w);
            H.z = packbf(v.x, v.y); H.w = packbf(v.z, v.w);
            L.x = packbf(bfres(u.x), bfres(u.y)); L.y = packbf(bfres(u.z), bfres(u.w));
            L.z = packbf(bfres(v.x), bfres(v.y)); L.w = packbf(bfres(v.z), bfres(v.w));
            uint32_t off = (uint32_t)(tid * 128) + ((uint32_t)(cb ^ (tid & 7)) << 4);
            *(uint4*)(smem + AQH + off) = H;
            *(uint4*)(smem + AQL + off) = L;
        }
    }
    // ---- K tiles (rows >= SCTX zero-filled; 96 rows) ----
    for (int idx = tid; idx < 96 * 8; idx += 128) {
        int r = idx >> 3, cb = idx & 7;
        float4 u = {0,0,0,0}, v = {0,0,0,0};
        if (r < SCTX) {
            const float4* kp = (const float4*)(g_k + ((size_t)bh * SCTX + r) * DH + cb * 8);
            u = kp[0]; v = kp[1];
        }
        uint4 H, L;
        H.x = packbf(u.x, u.y); H.y = packbf(u.z, u.w);
        H.z = packbf(v.x, v.y); H.w = packbf(v.z, v.w);
        L.x = packbf(bfres(u.x), bfres(u.y)); L.y = packbf(bfres(u.z), bfres(u.w));
        L.z = packbf(bfres(v.x), bfres(v.y)); L.w = packbf(bfres(v.z), bfres(v.w));
        uint32_t off = (uint32_t)(r * 128) + ((uint32_t)(cb ^ (r & 7)) << 4);
        *(uint4*)(smem + AKH + off) = H;
        *(uint4*)(smem + AKL + off) = L;
    }
    // ---- Vt tiles: Vt[d][s], rows 208B ----
    for (int idx = tid; idx < 64 * 12; idx += 128) {
        int d = idx / 12, sc = idx % 12;
        float vals[8];
#pragma unroll
        for (int j = 0; j < 8; ++j) {
            int s = sc * 8 + j;
            vals[j] = (s < SCTX) ? g_v[((size_t)bh * SCTX + s) * DH + d] : 0.f;
        }
        uint4 H, L;
        H.x = packbf(vals[0], vals[1]); H.y = packbf(vals[2], vals[3]);
        H.z = packbf(vals[4], vals[5]); H.w = packbf(vals[6], vals[7]);
        L.x = packbf(bfres(vals[0]), bfres(vals[1]));
        L.y = packbf(bfres(vals[2]), bfres(vals[3]));
        L.z = packbf(bfres(vals[4]), bfres(vals[5]));
        L.w = packbf(bfres(vals[6]), bfres(vals[7]));
        uint32_t off = (uint32_t)(d * 208 + sc * 16);
        *(uint4*)(smem + AVH + off) = H;
        *(uint4*)(smem + AVL + off) = L;
    }
    __syncthreads();

    // ---- QK^T : logits L[2][12][4] (q m-tiles x s n-tiles) ----
    float Lg[2][12][4];
#pragma unroll
    for (int mi = 0; mi < 2; ++mi)
#pragma unroll
        for (int j = 0; j < 12; ++j)
#pragma unroll
            for (int v = 0; v < 4; ++v) Lg[mi][j][v] = 0.f;

#pragma unroll
    for (int kc = 0; kc < 4; ++kc) {
        uint32_t qa_h[2][4], qa_l[2][4];
#pragma unroll
        for (int mi = 0; mi < 2; ++mi) {
            uint32_t row = (uint32_t)(w * 32 + mi * 16 + (lane & 15));
            uint32_t byte = row * 128
                + (((uint32_t)(kc * 32) + ((uint32_t)(lane >> 4) << 4))
                   ^ ((row & 7) << 4));
            ldsm_x4(sb + AQH + byte, qa_h[mi][0], qa_h[mi][1], qa_h[mi][2], qa_h[mi][3]);
            ldsm_x4(sb + AQL + byte, qa_l[mi][0], qa_l[mi][1], qa_l[mi][2], qa_l[mi][3]);
        }
        uint32_t kb_h[12][2], kb_l[12][2];
#pragma unroll
        for (int bt = 0; bt < 6; ++bt) {
            uint32_t row = (uint32_t)(bt * 16 + ((lane >> 4) << 3) + (lane & 7));
            uint32_t byte = row * 128
                + (((uint32_t)(kc * 32) + (((uint32_t)(lane >> 3) & 1) << 4))
                   ^ ((row & 7) << 4));
            ldsm_x4(sb + AKH + byte, kb_h[bt*2][0], kb_h[bt*2][1],
                                     kb_h[bt*2+1][0], kb_h[bt*2+1][1]);
            ldsm_x4(sb + AKL + byte, kb_l[bt*2][0], kb_l[bt*2][1],
                                     kb_l[bt*2+1][0], kb_l[bt*2+1][1]);
        }
#pragma unroll
        for (int mi = 0; mi < 2; ++mi)
#pragma unroll
            for (int j = 0; j < 12; ++j) {
                mma_bf16(Lg[mi][j], qa_h[mi], kb_h[j]);
                mma_bf16(Lg[mi][j], qa_h[mi], kb_l[j]);
                mma_bf16(Lg[mi][j], qa_l[mi], kb_h[j]);
            }
    }

    // ---- two-segment softmax on fragments ----
    const int c0 = 2 * (lane & 3);
#pragma unroll
    for (int mi = 0; mi < 2; ++mi) {
#pragma unroll
        for (int half = 0; half < 2; ++half) {
            float mx1 = -1e30f, mx2 = -1e30f;
#pragma unroll
            for (int j = 0; j < 12; ++j)
#pragma unroll
                for (int u = 0; u < 2; ++u) {
                    int col = j * 8 + c0 + u;
                    float v = Lg[mi][j][half * 2 + u] * 0.125f;
                    Lg[mi][j][half * 2 + u] = v;
                    if (col < SCTX) {
                        if (col < eos) mx1 = fmaxf(mx1, v);
                        else           mx2 = fmaxf(mx2, v);
                    }
                }
            mx1 = fmaxf(mx1, __shfl_xor_sync(0xffffffffu, mx1, 1));
            mx1 = fmaxf(mx1, __shfl_xor_sync(0xffffffffu, mx1, 2));
            mx2 = fmaxf(mx2, __shfl_xor_sync(0xffffffffu, mx2, 1));
            mx2 = fmaxf(mx2, __shfl_xor_sync(0xffffffffu, mx2, 2));
            float s1 = 0.f, s2 = 0.f;
#pragma unroll
            for (int j = 0; j < 12; ++j)
#pragma unroll
                for (int u = 0; u < 2; ++u) {
                    int col = j * 8 + c0 + u;
                    float v = Lg[mi][j][half * 2 + u];
                    if (col < SCTX) {
                        if (col < eos) s1 += __expf(v - mx1);
                        else           s2 += __expf(v - mx2);
                    }
                }
            s1 += __shfl_xor_sync(0xffffffffu, s1, 1);
            s1 += __shfl_xor_sync(0xffffffffu, s1, 2);
            s2 += __shfl_xor_sync(0xffffffffu, s2, 1);
            s2 += __shfl_xor_sync(0xffffffffu, s2, 2);
            float w1 = (s1 > 0.f) ? 1.f / s1 : 0.f;
            float w2 = (s2 > 0.f) ? ipscale / s2 : 0.f;
#pragma unroll
            for (int j = 0; j < 12; ++j)
#pragma unroll
                for (int u = 0; u < 2; ++u) {
                    int col = j * 8 + c0 + u;
                    float v = Lg[mi][j][half * 2 + u];
                    float p = 0.f;
                    if (col < SCTX)
                        p = (col < eos) ? __expf(v - mx1) * w1
                                        : __expf(v - mx2) * w2;
                    Lg[mi][j][half * 2 + u] = p;
                }
        }
    }

    // ---- P * V ----
    float o[2][8][4];
#pragma unroll
    for (int mi = 0; mi < 2; ++mi)
#pragma unroll
        for (int nd = 0; nd < 8; ++nd)
#pragma unroll
            for (int v = 0; v < 4; ++v) o[mi][nd][v] = 0.f;

#pragma unroll
    for (int kc = 0; kc < 6; ++kc) {
        uint32_t vb_h[8][2], vb_l[8][2];
#pragma unroll
        for (int dt = 0; dt < 4; ++dt) {
            uint32_t row = (uint32_t)(dt * 16 + ((lane >> 4) << 3) + (lane & 7));
            uint32_t byte = row * 208 + (uint32_t)(kc * 32)
                          + (((uint32_t)(lane >> 3) & 1) << 4);
            ldsm_x4(sb + AVH + byte, vb_h[dt*2][0], vb_h[dt*2][1],
                                     vb_h[dt*2+1][0], vb_h[dt*2+1][1]);
            ldsm_x4(sb + AVL + byte, vb_l[dt*2][0], vb_l[dt*2][1],
                                     vb_l[dt*2+1][0], vb_l[dt*2+1][1]);
        }
#pragma unroll
        for (int mi = 0; mi < 2; ++mi) {
            const float* p0 = Lg[mi][2 * kc];
            const float* p1 = Lg[mi][2 * kc + 1];
            uint32_t pa_h[4], pa_l[4];
            pa_h[0] = packbf(p0[0], p0[1]);
            pa_h[1] = packbf(p0[2], p0[3]);
            pa_h[2] = packbf(p1[0], p1[1]);
            pa_h[3] = packbf(p1[2], p1[3]);
            pa_l[0] = packbf(bfres(p0[0]), bfres(p0[1]));
            pa_l[1] = packbf(bfres(p0[2]), bfres(p0[3]));
            pa_l[2] = packbf(bfres(p1[0]), bfres(p1[1]));
            pa_l[3] = packbf(bfres(p1[2]), bfres(p1[3]));
#pragma unroll
            for (int nd = 0; nd < 8; ++nd) {
                mma_bf16(o[mi][nd], pa_h, vb_h[nd]);
                mma_bf16(o[mi][nd], pa_h, vb_l[nd]);
                mma_bf16(o[mi][nd], pa_l, vb_h[nd]);
            }
        }
    }

    // ---- epilogue: bf16 hi/lo splits to g_ah/g_al ----
#pragma unroll
    for (int mi = 0; mi < 2; ++mi) {
        const int r0 = q0 + w * 32 + mi * 16 + (lane >> 2);
#pragma unroll
        for (int nd = 0; nd < 8; ++nd) {
            const int d = nd * 8 + c0;
            size_t base0 = ((size_t)b * SQ + r0) * INNER + h * DH + d;
            size_t base1 = base0 + (size_t)8 * INNER;
            float a0 = o[mi][nd][0], a1 = o[mi][nd][1];
            float a2 = o[mi][nd][2], a3 = o[mi][nd][3];
            *(uint32_t*)(g_ah + base0) = packbf(a0, a1);
            *(uint32_t*)(g_al + base0) = packbf(bfres(a0), bfres(a1));
            *(uint32_t*)(g_ah + base1) = packbf(a2, a3);
            *(uint32_t*)(g_al + base1) = packbf(bfres(a2), bfres(a3));
        }
    }
}

// ---------------------------------------------------------------------------
// Launch: x, context, scale, num_img_token, Wq, Wk, Wv, Wk_ip, Wv_ip, Wout, b_out
// ---------------------------------------------------------------------------
extern "C" void kernel_launch(void* const* d_in, const int* in_sizes, int n_in,
                              void* d_out, int out_size)
{
    const float* x     = (const float*)d_in[0];
    const float* ctx   = (const float*)d_in[1];
    const float* scale = (const float*)d_in[2];
    const int*   nimg  = (const int*)  d_in[3];
    const float* Wq    = (const float*)d_in[4];
    const float* Wk    = (const float*)d_in[5];
    const float* Wv    = (const float*)d_in[6];
    const float* Wki   = (const float*)d_in[7];
    const float* Wvi   = (const float*)d_in[8];
    const float* Wout  = (const float*)d_in[9];
    const float* bout  = (const float*)d_in[10];
    float*       out   = (float*)d_out;

    float *qp;
    __nv_bfloat16 *xh, *xl, *ah, *al, *wqh, *wql, *woh, *wol;
    cudaGetSymbolAddress((void**)&qp,  g_q);
    cudaGetSymbolAddress((void**)&xh,  g_xh);
    cudaGetSymbolAddress((void**)&xl,  g_xl);
    cudaGetSymbolAddress((void**)&ah,  g_ah);
    cudaGetSymbolAddress((void**)&al,  g_al);
    cudaGetSymbolAddress((void**)&wqh, g_wqh);
    cudaGetSymbolAddress((void**)&wql, g_wql);
    cudaGetSymbolAddress((void**)&woh, g_woh);
    cudaGetSymbolAddress((void**)&wol, g_wol);

    cudaFuncSetAttribute(attn_mma,
        cudaFuncAttributeMaxDynamicSharedMemorySize, ATTN_SMEM);
    cudaFuncSetAttribute(gemm_hmma<true, false>,
        cudaFuncAttributeMaxDynamicSharedMemorySize, GEMM_SMEM);
    cudaFuncSetAttribute(gemm_hmma<false, true>,
        cudaFuncAttributeMaxDynamicSharedMemorySize, GEMM_SMEM);

    // conversions
    split_bf16<<<4096, 256>>>((const float4*)x, (ushort4*)xh, (ushort4*)xl,
                              (int)((size_t)BB * SQ * QD / 4));
    split_bf16<<<1600, 256>>>((const float4*)Wq, (ushort4*)wqh, (ushort4*)wql,
                              INNER * QD / 4);
    split_bf16<<<1600, 256>>>((const float4*)Wout, (ushort4*)woh, (ushort4*)wol,
                              QD * INNER / 4);

    // K/V projections
    kv_proj_kernel<<<dim3(NH, BB), 512>>>(ctx, Wk, Wv, Wki, Wvi, nimg);

    // Q projection (HMMA bf16x3), scattered into [b,h,s,d]
    gemm_hmma<true, false><<<dim3(INNER / 128, (BB * SQ) / 128), 256, GEMM_SMEM>>>(
        xh, xl, wqh, wql, nullptr, qp, QD);

    // HMMA flash-style two-segment attention -> bf16 hi/lo
    attn_mma<<<dim3(BB * NH, SQ / 128), 128, ATTN_SMEM>>>(scale, nimg);

    // output projection + bias (HMMA bf16x3)
    gemm_hmma<false, true><<<dim3(QD / 128, (BB * SQ) / 128), 256, GEMM_SMEM>>>(
        ah, al, woh, wol, bout, out, INNER);
}

// round 6
// speedup vs baseline: 3.3787x; 1.3893x over previous
#include <cuda_runtime.h>
#include <cuda_bf16.h>
#include <cuda_fp16.h>
#include <cstdint>
#include <cstddef>

// Problem constants
#define BB    8
#define SQ    4096
#define QD    1280
#define SCTX  93
#define CD    2048
#define NH    20
#define DH    64
#define INNER 1280

// ---------------------------------------------------------------------------
// Scratch (__device__ globals; no allocs allowed)
// ---------------------------------------------------------------------------
__device__ float  g_q   [(size_t)BB * SQ * NH * DH];   // Q fp32 [b,h,s,d]
__device__ __half g_x16 [(size_t)BB * SQ * QD];
__device__ __half g_a16 [(size_t)BB * SQ * INNER];     // attn out fp16 [b,s,i]
__device__ __half g_wq16[(size_t)INNER * QD];
__device__ __half g_wo16[(size_t)QD * INNER];
__device__ float  g_k[(size_t)BB * NH * SCTX * DH];
__device__ float  g_v[(size_t)BB * NH * SCTX * DH];

// ---------------------------------------------------------------------------
// Helpers (arch-agnostic PTX only: cp.async, ldmatrix, mma.sync)
// ---------------------------------------------------------------------------
__device__ __forceinline__ uint32_t smem_u32(const void* p) {
    uint32_t a;
    asm("{ .reg .u64 t; cvta.to.shared.u64 t, %1; cvt.u32.u64 %0, t; }"
        : "=r"(a) : "l"(p));
    return a;
}
#define CP_COMMIT() asm volatile("cp.async.commit_group;" ::: "memory")
#define CP_WAIT(n)  asm volatile("cp.async.wait_group %0;" :: "n"(n) : "memory")

__device__ __forceinline__ void ldsm_x4(uint32_t addr, uint32_t& r0, uint32_t& r1,
                                        uint32_t& r2, uint32_t& r3) {
    asm volatile("ldmatrix.sync.aligned.m8n8.x4.shared.b16 {%0,%1,%2,%3}, [%4];"
                 : "=r"(r0), "=r"(r1), "=r"(r2), "=r"(r3) : "r"(addr));
}
__device__ __forceinline__ void mma_bf16(float* c, const uint32_t* a,
                                         const uint32_t* b) {
    asm volatile(
        "mma.sync.aligned.m16n8k16.row.col.f32.bf16.bf16.f32 "
        "{%0,%1,%2,%3}, {%4,%5,%6,%7}, {%8,%9}, {%0,%1,%2,%3};"
        : "+f"(c[0]), "+f"(c[1]), "+f"(c[2]), "+f"(c[3])
        : "r"(a[0]), "r"(a[1]), "r"(a[2]), "r"(a[3]), "r"(b[0]), "r"(b[1]));
}
__device__ __forceinline__ void mma_fp16(float* c, const uint32_t* a,
                                         const uint32_t* b) {
    asm volatile(
        "mma.sync.aligned.m16n8k16.row.col.f32.f16.f16.f32 "
        "{%0,%1,%2,%3}, {%4,%5,%6,%7}, {%8,%9}, {%0,%1,%2,%3};"
        : "+f"(c[0]), "+f"(c[1]), "+f"(c[2]), "+f"(c[3])
        : "r"(a[0]), "r"(a[1]), "r"(a[2]), "r"(a[3]), "r"(b[0]), "r"(b[1]));
}
__device__ __forceinline__ uint32_t packbf(float x, float y) {
    __nv_bfloat162 t = __floats2bfloat162_rn(x, y);
    return *(uint32_t*)&t;
}
__device__ __forceinline__ uint32_t packhf(float x, float y) {
    __half2 t = __floats2half2_rn(x, y);
    return *(uint32_t*)&t;
}
__device__ __forceinline__ float bfres(float x) {
    return x - __bfloat162float(__float2bfloat16(x));
}

// ---------------------------------------------------------------------------
// fp32 -> fp16 cast
// ---------------------------------------------------------------------------
__global__ void to_fp16(const float4* __restrict__ src,
                        ushort4* __restrict__ dst, int n4)
{
    for (int i = blockIdx.x * blockDim.x + threadIdx.x; i < n4;
         i += gridDim.x * blockDim.x) {
        float4 v = src[i];
        ushort4 o;
        o.x = __half_as_ushort(__float2half_rn(v.x));
        o.y = __half_as_ushort(__float2half_rn(v.y));
        o.z = __half_as_ushort(__float2half_rn(v.z));
        o.w = __half_as_ushort(__float2half_rn(v.w));
        dst[i] = o;
    }
}

// ---------------------------------------------------------------------------
// KV projections (fp32, small)
// ---------------------------------------------------------------------------
__global__ void __launch_bounds__(512) kv_proj_kernel(
    const float* __restrict__ ctx,
    const float* __restrict__ Wk,  const float* __restrict__ Wv,
    const float* __restrict__ Wki, const float* __restrict__ Wvi,
    const int*   __restrict__ nimg_p)
{
    __shared__ float cs[96][17];
    __shared__ float wk_s[64][17], wv_s[64][17], wki_s[64][17], wvi_s[64][17];

    const int tid = threadIdx.x;
    const int b   = blockIdx.y;
    const int hh  = blockIdx.x;
    const int n0  = hh * 64;
    const int eos = SCTX - *nimg_p;
    const int n   = tid & 63;
    const int g   = tid >> 6;

    float ak[12], av[12];
#pragma unroll
    for (int j = 0; j < 12; ++j) { ak[j] = 0.f; av[j] = 0.f; }

    for (int k0 = 0; k0 < CD; k0 += 16) {
        __syncthreads();
        for (int i = tid; i < 96 * 16; i += 512) {
            int s = i >> 4, kk = i & 15;
            cs[s][kk] = (s < SCTX) ? ctx[((size_t)b * SCTX + s) * CD + k0 + kk] : 0.f;
        }
        for (int i = tid; i < 64 * 16; i += 512) {
            int r = i >> 4, kk = i & 15;
            size_t gi = (size_t)(n0 + r) * CD + k0 + kk;
            wk_s [r][kk] = Wk [gi]; wv_s [r][kk] = Wv [gi];
            wki_s[r][kk] = Wki[gi]; wvi_s[r][kk] = Wvi[gi];
        }
        __syncthreads();
#pragma unroll
        for (int kk = 0; kk < 16; ++kk) {
            float wkv = wk_s[n][kk],  wvv = wv_s[n][kk];
            float wkiv = wki_s[n][kk], wviv = wvi_s[n][kk];
#pragma unroll
            for (int j = 0; j < 12; ++j) {
                int s = g * 12 + j;
                float c = cs[s][kk];
                bool txt = (s < eos);
                ak[j] = fmaf(c, txt ? wkv : wkiv, ak[j]);
                av[j] = fmaf(c, txt ? wvv : wviv, av[j]);
            }
        }
    }
    size_t base = ((size_t)(b * NH + hh) * SCTX) * DH + n;
#pragma unroll
    for (int j = 0; j < 12; ++j) {
        int s = g * 12 + j;
        if (s < SCTX) {
            g_k[base + (size_t)s * DH] = ak[j];
            g_v[base + (size_t)s * DH] = av[j];
        }
    }
}

// ---------------------------------------------------------------------------
// fp16 single-pass HMMA GEMM: C[m,n] = sum_k A[m,k]*B[n,k].
// 128x128 CTA tile, 8 warps (2m x 4n), K-chunk 32, 3-stage cp.async pipeline.
// Stage = A tile (8KB) + B tile (8KB); swizzle: cb ^ ((r>>1)&3) per 16B col.
// ---------------------------------------------------------------------------
#define GEMM_STAGES 3
#define TILE_BYTES  8192
#define STAGE_BYTES (2 * TILE_BYTES)
#define GEMM_SMEM   (GEMM_STAGES * STAGE_BYTES)

__device__ __forceinline__ void load_tiles16(
    uint32_t sbase,
    const __half* __restrict__ A, const __half* __restrict__ B,
    int m0, int n0, int k0, int K, int tid)
{
#pragma unroll
    for (int i = 0; i < 4; ++i) {
        int idx = tid + (i << 8);            // 0..1023 16B chunks
        int mat = idx >> 9;                  // 0:A 1:B
        int w   = idx & 511;
        int r   = w >> 2;
        int cb  = w & 3;
        int grow = ((mat == 0) ? m0 : n0) + r;
        const __half* base = (mat == 0) ? A : B;
        const char* src = (const char*)(base + (size_t)grow * K + k0) + (cb << 4);
        uint32_t dst = sbase + (mat << 13) + (r << 6)
                     + (uint32_t)((cb ^ ((r >> 1) & 3)) << 4);
        asm volatile("cp.async.cg.shared.global [%0], [%1], 16;"
                     :: "r"(dst), "l"(src) : "memory");
    }
}

template <bool REMAP_Q, bool HAS_BIAS>
__global__ void __launch_bounds__(256, 2) gemm_fp16(
    const __half* __restrict__ A, const __half* __restrict__ B,
    const float* __restrict__ bias, float* __restrict__ C, int K)
{
    extern __shared__ __align__(128) char smem[];
    const uint32_t sb = smem_u32(smem);
    const int tid  = threadIdx.x;
    const int wid  = tid >> 5;
    const int lane = tid & 31;
    const int mw   = wid >> 2;
    const int nw   = wid & 3;
    const int n0   = blockIdx.x << 7;
    const int m0   = blockIdx.y << 7;
    const int NCH  = K >> 5;

    uint32_t aoff[4], axor[4];
#pragma unroll
    for (int mi = 0; mi < 4; ++mi) {
        uint32_t rA = (uint32_t)(mw * 64 + mi * 16 + (lane & 15));
        aoff[mi] = rA << 6;
        axor[mi] = (rA >> 1) & 3;
    }
    uint32_t boff[2], bxor[2];
#pragma unroll
    for (int bt = 0; bt < 2; ++bt) {
        uint32_t rB = (uint32_t)(nw * 32 + bt * 16 + ((lane >> 4) << 3)
                                 + (lane & 7));
        boff[bt] = rB << 6;
        bxor[bt] = (rB >> 1) & 3;
    }
    const uint32_t cA = (uint32_t)(lane >> 4);
    const uint32_t cB = (uint32_t)((lane >> 3) & 1);

    float acc[4][4][4];
#pragma unroll
    for (int i = 0; i < 4; ++i)
#pragma unroll
        for (int j = 0; j < 4; ++j)
#pragma unroll
            for (int v = 0; v < 4; ++v) acc[i][j][v] = 0.f;

#pragma unroll
    for (int c = 0; c < GEMM_STAGES - 1; ++c) {
        load_tiles16(sb + c * STAGE_BYTES, A, B, m0, n0, c << 5, K, tid);
        CP_COMMIT();
    }

    int s = 0;
    for (int c = 0; c < NCH; ++c) {
        CP_WAIT(1);
        __syncthreads();

        if (c + GEMM_STAGES - 1 < NCH) {
            int sn = c + GEMM_STAGES - 1;
            load_tiles16(sb + (sn % GEMM_STAGES) * STAGE_BYTES, A, B,
                         m0, n0, sn << 5, K, tid);
        }
        CP_COMMIT();

        const uint32_t bA = sb + s * STAGE_BYTES;
        const uint32_t bB = bA + TILE_BYTES;

#pragma unroll
        for (int t = 0; t < 2; ++t) {
            const uint32_t cbA = (uint32_t)(2 * t) + cA;
            const uint32_t cbB = (uint32_t)(2 * t) + cB;

            uint32_t a[4][4], b[4][2];
#pragma unroll
            for (int mi = 0; mi < 4; ++mi) {
                uint32_t off = aoff[mi] + ((cbA ^ axor[mi]) << 4);
                ldsm_x4(bA + off, a[mi][0], a[mi][1], a[mi][2], a[mi][3]);
            }
#pragma unroll
            for (int bt = 0; bt < 2; ++bt) {
                uint32_t off = boff[bt] + ((cbB ^ bxor[bt]) << 4);
                ldsm_x4(bB + off, b[bt*2][0], b[bt*2][1],
                                  b[bt*2+1][0], b[bt*2+1][1]);
            }
#pragma unroll
            for (int mi = 0; mi < 4; ++mi)
#pragma unroll
                for (int ni = 0; ni < 4; ++ni)
                    mma_fp16(acc[mi][ni], a[mi], b[ni]);
        }
        s = (s == GEMM_STAGES - 1) ? 0 : s + 1;
    }

#pragma unroll
    for (int mi = 0; mi < 4; ++mi) {
        const int mbase = m0 + mw * 64 + mi * 16 + (lane >> 2);
#pragma unroll
        for (int ni = 0; ni < 4; ++ni) {
            const int n = n0 + nw * 32 + ni * 8 + (lane & 3) * 2;
            float2 v0, v1;
            v0.x = acc[mi][ni][0]; v0.y = acc[mi][ni][1];
            v1.x = acc[mi][ni][2]; v1.y = acc[mi][ni][3];
            if (HAS_BIAS) {
                float b0 = bias[n], b1 = bias[n + 1];
                v0.x += b0; v0.y += b1; v1.x += b0; v1.y += b1;
            }
            if (REMAP_Q) {
                const int h = n >> 6, d = n & 63;
                const int b0i = mbase >> 12, s0 = mbase & 4095;
                float* p0 = g_q + (((size_t)(b0i * NH + h) * SQ + s0) * DH + d);
                const int m1 = mbase + 8;
                const int b1i = m1 >> 12, s1 = m1 & 4095;
                float* p1 = g_q + (((size_t)(b1i * NH + h) * SQ + s1) * DH + d);
                *(float2*)p0 = v0;
                *(float2*)p1 = v1;
            } else {
                *(float2*)(C + (size_t)mbase * QD + n) = v0;
                *(float2*)(C + (size_t)(mbase + 8) * QD + n) = v1;
            }
        }
    }
}

// ---------------------------------------------------------------------------
// HMMA flash-style two-segment attention (bf16x3 internally; fp16 output).
// Block = 128 threads (4 warps), handles (bh, 128 q-rows).
// ---------------------------------------------------------------------------
#define AQH  0
#define AQL  16384
#define AKH  32768
#define AKL  45056
#define AVH  57344
#define AVL  70656
#define ATTN_SMEM 83968

__global__ void __launch_bounds__(128) attn_mma(
    const float* __restrict__ scale_p, const int* __restrict__ nimg_p)
{
    extern __shared__ __align__(128) char smem[];
    const uint32_t sb = smem_u32(smem);
    const int tid  = threadIdx.x;
    const int lane = tid & 31;
    const int w    = tid >> 5;
    const int bh   = blockIdx.x;
    const int q0   = blockIdx.y << 7;
    const int b    = bh / NH;
    const int h    = bh % NH;
    const int eos  = SCTX - *nimg_p;
    const float ipscale = *scale_p;

    // Q tiles
    {
        const float4* src = (const float4*)(g_q + ((size_t)bh * SQ + q0 + tid) * DH);
#pragma unroll
        for (int cb = 0; cb < 8; ++cb) {
            float4 u = src[cb * 2], v = src[cb * 2 + 1];
            uint4 H, L;
            H.x = packbf(u.x, u.y); H.y = packbf(u.z, u.w);
            H.z = packbf(v.x, v.y); H.w = packbf(v.z, v.w);
            L.x = packbf(bfres(u.x), bfres(u.y)); L.y = packbf(bfres(u.z), bfres(u.w));
            L.z = packbf(bfres(v.x), bfres(v.y)); L.w = packbf(bfres(v.z), bfres(v.w));
            uint32_t off = (uint32_t)(tid * 128) + ((uint32_t)(cb ^ (tid & 7)) << 4);
            *(uint4*)(smem + AQH + off) = H;
            *(uint4*)(smem + AQL + off) = L;
        }
    }
    // K tiles
    for (int idx = tid; idx < 96 * 8; idx += 128) {
        int r = idx >> 3, cb = idx & 7;
        float4 u = {0,0,0,0}, v = {0,0,0,0};
        if (r < SCTX) {
            const float4* kp = (const float4*)(g_k + ((size_t)bh * SCTX + r) * DH + cb * 8);
            u = kp[0]; v = kp[1];
        }
        uint4 H, L;
        H.x = packbf(u.x, u.y); H.y = packbf(u.z, u.w);
        H.z = packbf(v.x, v.y); H.w = packbf(v.z, v.w);
        L.x = packbf(bfres(u.x), bfres(u.y)); L.y = packbf(bfres(u.z), bfres(u.w));
        L.z = packbf(bfres(v.x), bfres(v.y)); L.w = packbf(bfres(v.z), bfres(v.w));
        uint32_t off = (uint32_t)(r * 128) + ((uint32_t)(cb ^ (r & 7)) << 4);
        *(uint4*)(smem + AKH + off) = H;
        *(uint4*)(smem + AKL + off) = L;
    }
    // Vt tiles
    for (int idx = tid; idx < 64 * 12; idx += 128) {
        int d = idx / 12, sc = idx % 12;
        float vals[8];
#pragma unroll
        for (int j = 0; j < 8; ++j) {
            int s = sc * 8 + j;
            vals[j] = (s < SCTX) ? g_v[((size_t)bh * SCTX + s) * DH + d] : 0.f;
        }
        uint4 H, L;
        H.x = packbf(vals[0], vals[1]); H.y = packbf(vals[2], vals[3]);
        H.z = packbf(vals[4], vals[5]); H.w = packbf(vals[6], vals[7]);
        L.x = packbf(bfres(vals[0]), bfres(vals[1]));
        L.y = packbf(bfres(vals[2]), bfres(vals[3]));
        L.z = packbf(bfres(vals[4]), bfres(vals[5]));
        L.w = packbf(bfres(vals[6]), bfres(vals[7]));
        uint32_t off = (uint32_t)(d * 208 + sc * 16);
        *(uint4*)(smem + AVH + off) = H;
        *(uint4*)(smem + AVL + off) = L;
    }
    __syncthreads();

    // QK^T
    float Lg[2][12][4];
#pragma unroll
    for (int mi = 0; mi < 2; ++mi)
#pragma unroll
        for (int j = 0; j < 12; ++j)
#pragma unroll
            for (int v = 0; v < 4; ++v) Lg[mi][j][v] = 0.f;

#pragma unroll
    for (int kc = 0; kc < 4; ++kc) {
        uint32_t qa_h[2][4], qa_l[2][4];
#pragma unroll
        for (int mi = 0; mi < 2; ++mi) {
            uint32_t row = (uint32_t)(w * 32 + mi * 16 + (lane & 15));
            uint32_t byte = row * 128
                + (((uint32_t)(kc * 32) + ((uint32_t)(lane >> 4) << 4))
                   ^ ((row & 7) << 4));
            ldsm_x4(sb + AQH + byte, qa_h[mi][0], qa_h[mi][1], qa_h[mi][2], qa_h[mi][3]);
            ldsm_x4(sb + AQL + byte, qa_l[mi][0], qa_l[mi][1], qa_l[mi][2], qa_l[mi][3]);
        }
        uint32_t kb_h[12][2], kb_l[12][2];
#pragma unroll
        for (int bt = 0; bt < 6; ++bt) {
            uint32_t row = (uint32_t)(bt * 16 + ((lane >> 4) << 3) + (lane & 7));
            uint32_t byte = row * 128
                + (((uint32_t)(kc * 32) + (((uint32_t)(lane >> 3) & 1) << 4))
                   ^ ((row & 7) << 4));
            ldsm_x4(sb + AKH + byte, kb_h[bt*2][0], kb_h[bt*2][1],
                                     kb_h[bt*2+1][0], kb_h[bt*2+1][1]);
            ldsm_x4(sb + AKL + byte, kb_l[bt*2][0], kb_l[bt*2][1],
                                     kb_l[bt*2+1][0], kb_l[bt*2+1][1]);
        }
#pragma unroll
        for (int mi = 0; mi < 2; ++mi)
#pragma unroll
            for (int j = 0; j < 12; ++j) {
                mma_bf16(Lg[mi][j], qa_h[mi], kb_h[j]);
                mma_bf16(Lg[mi][j], qa_h[mi], kb_l[j]);
                mma_bf16(Lg[mi][j], qa_l[mi], kb_h[j]);
            }
    }

    // two-segment softmax
    const int c0 = 2 * (lane & 3);
#pragma unroll
    for (int mi = 0; mi < 2; ++mi) {
#pragma unroll
        for (int half = 0; half < 2; ++half) {
            float mx1 = -1e30f, mx2 = -1e30f;
#pragma unroll
            for (int j = 0; j < 12; ++j)
#pragma unroll
                for (int u = 0; u < 2; ++u) {
                    int col = j * 8 + c0 + u;
                    float v = Lg[mi][j][half * 2 + u] * 0.125f;
                    Lg[mi][j][half * 2 + u] = v;
                    if (col < SCTX) {
                        if (col < eos) mx1 = fmaxf(mx1, v);
                        else           mx2 = fmaxf(mx2, v);
                    }
                }
            mx1 = fmaxf(mx1, __shfl_xor_sync(0xffffffffu, mx1, 1));
            mx1 = fmaxf(mx1, __shfl_xor_sync(0xffffffffu, mx1, 2));
            mx2 = fmaxf(mx2, __shfl_xor_sync(0xffffffffu, mx2, 1));
            mx2 = fmaxf(mx2, __shfl_xor_sync(0xffffffffu, mx2, 2));
            float s1 = 0.f, s2 = 0.f;
#pragma unroll
            for (int j = 0; j < 12; ++j)
#pragma unroll
                for (int u = 0; u < 2; ++u) {
                    int col = j * 8 + c0 + u;
                    float v = Lg[mi][j][half * 2 + u];
                    if (col < SCTX) {
                        if (col < eos) s1 += __expf(v - mx1);
                        else           s2 += __expf(v - mx2);
                    }
                }
            s1 += __shfl_xor_sync(0xffffffffu, s1, 1);
            s1 += __shfl_xor_sync(0xffffffffu, s1, 2);
            s2 += __shfl_xor_sync(0xffffffffu, s2, 1);
            s2 += __shfl_xor_sync(0xffffffffu, s2, 2);
            float w1 = (s1 > 0.f) ? 1.f / s1 : 0.f;
            float w2 = (s2 > 0.f) ? ipscale / s2 : 0.f;
#pragma unroll
            for (int j = 0; j < 12; ++j)
#pragma unroll
                for (int u = 0; u < 2; ++u) {
                    int col = j * 8 + c0 + u;
                    float v = Lg[mi][j][half * 2 + u];
                    float p = 0.f;
                    if (col < SCTX)
                        p = (col < eos) ? __expf(v - mx1) * w1
                                        : __expf(v - mx2) * w2;
                    Lg[mi][j][half * 2 + u] = p;
                }
        }
    }

    // P * V
    float o[2][8][4];
#pragma unroll
    for (int mi = 0; mi < 2; ++mi)
#pragma unroll
        for (int nd = 0; nd < 8; ++nd)
#pragma unroll
            for (int v = 0; v < 4; ++v) o[mi][nd][v] = 0.f;

#pragma unroll
    for (int kc = 0; kc < 6; ++kc) {
        uint32_t vb_h[8][2], vb_l[8][2];
#pragma unroll
        for (int dt = 0; dt < 4; ++dt) {
            uint32_t row = (uint32_t)(dt * 16 + ((lane >> 4) << 3) + (lane & 7));
            uint32_t byte = row * 208 + (uint32_t)(kc * 32)
                          + (((uint32_t)(lane >> 3) & 1) << 4);
            ldsm_x4(sb + AVH + byte, vb_h[dt*2][0], vb_h[dt*2][1],
                                     vb_h[dt*2+1][0], vb_h[dt*2+1][1]);
            ldsm_x4(sb + AVL + byte, vb_l[dt*2][0], vb_l[dt*2][1],
                                     vb_l[dt*2+1][0], vb_l[dt*2+1][1]);
        }
#pragma unroll
        for (int mi = 0; mi < 2; ++mi) {
            const float* p0 = Lg[mi][2 * kc];
            const float* p1 = Lg[mi][2 * kc + 1];
            uint32_t pa_h[4], pa_l[4];
            pa_h[0] = packbf(p0[0], p0[1]);
            pa_h[1] = packbf(p0[2], p0[3]);
            pa_h[2] = packbf(p1[0], p1[1]);
            pa_h[3] = packbf(p1[2], p1[3]);
            pa_l[0] = packbf(bfres(p0[0]), bfres(p0[1]));
            pa_l[1] = packbf(bfres(p0[2]), bfres(p0[3]));
            pa_l[2] = packbf(bfres(p1[0]), bfres(p1[1]));
            pa_l[3] = packbf(bfres(p1[2]), bfres(p1[3]));
#pragma unroll
            for (int nd = 0; nd < 8; ++nd) {
                mma_bf16(o[mi][nd], pa_h, vb_h[nd]);
                mma_bf16(o[mi][nd], pa_h, vb_l[nd]);
                mma_bf16(o[mi][nd], pa_l, vb_h[nd]);
            }
        }
    }

    // epilogue: fp16 out
#pragma unroll
    for (int mi = 0; mi < 2; ++mi) {
        const int r0 = q0 + w * 32 + mi * 16 + (lane >> 2);
#pragma unroll
        for (int nd = 0; nd < 8; ++nd) {
            const int d = nd * 8 + c0;
            size_t base0 = ((size_t)b * SQ + r0) * INNER + h * DH + d;
            size_t base1 = base0 + (size_t)8 * INNER;
            *(uint32_t*)(g_a16 + base0) = packhf(o[mi][nd][0], o[mi][nd][1]);
            *(uint32_t*)(g_a16 + base1) = packhf(o[mi][nd][2], o[mi][nd][3]);
        }
    }
}

// ---------------------------------------------------------------------------
// Launch: x, context, scale, num_img_token, Wq, Wk, Wv, Wk_ip, Wv_ip, Wout, b_out
// ---------------------------------------------------------------------------
extern "C" void kernel_launch(void* const* d_in, const int* in_sizes, int n_in,
                              void* d_out, int out_size)
{
    const float* x     = (const float*)d_in[0];
    const float* ctx   = (const float*)d_in[1];
    const float* scale = (const float*)d_in[2];
    const int*   nimg  = (const int*)  d_in[3];
    const float* Wq    = (const float*)d_in[4];
    const float* Wout  = (const float*)d_in[9];
    const float* bout  = (const float*)d_in[10];
    float*       out   = (float*)d_out;

    float *qp;
    __half *x16, *a16, *wq16, *wo16;
    cudaGetSymbolAddress((void**)&qp,   g_q);
    cudaGetSymbolAddress((void**)&x16,  g_x16);
    cudaGetSymbolAddress((void**)&a16,  g_a16);
    cudaGetSymbolAddress((void**)&wq16, g_wq16);
    cudaGetSymbolAddress((void**)&wo16, g_wo16);

    cudaFuncSetAttribute(attn_mma,
        cudaFuncAttributeMaxDynamicSharedMemorySize, ATTN_SMEM);
    cudaFuncSetAttribute(gemm_fp16<true, false>,
        cudaFuncAttributeMaxDynamicSharedMemorySize, GEMM_SMEM);
    cudaFuncSetAttribute(gemm_fp16<false, true>,
        cudaFuncAttributeMaxDynamicSharedMemorySize, GEMM_SMEM);

    // conversions
    to_fp16<<<4096, 256>>>((const float4*)x, (ushort4*)x16,
                           (int)((size_t)BB * SQ * QD / 4));
    to_fp16<<<1600, 256>>>((const float4*)Wq, (ushort4*)wq16, INNER * QD / 4);
    to_fp16<<<1600, 256>>>((const float4*)Wout, (ushort4*)wo16, QD * INNER / 4);

    // K/V projections
    kv_proj_kernel<<<dim3(NH, BB), 512>>>(ctx,
        (const float*)d_in[5], (const float*)d_in[6],
        (const float*)d_in[7], (const float*)d_in[8], nimg);

    // Q projection (fp16 HMMA), scattered into [b,h,s,d] fp32
    gemm_fp16<true, false><<<dim3(INNER / 128, (BB * SQ) / 128), 256, GEMM_SMEM>>>(
        x16, wq16, nullptr, qp, QD);

    // flash-style two-segment attention (bf16x3) -> fp16
    attn_mma<<<dim3(BB * NH, SQ / 128), 128, ATTN_SMEM>>>(scale, nimg);

    // output projection + bias (fp16 HMMA)
    gemm_fp16<false, true><<<dim3(QD / 128, (BB * SQ) / 128), 256, GEMM_SMEM>>>(
        a16, wo16, bout, out, INNER);
}

// round 7
// speedup vs baseline: 3.5569x; 1.0528x over previous
#include <cuda_runtime.h>
#include <cuda_bf16.h>
#include <cuda_fp16.h>
#include <cstdint>
#include <cstddef>

// Problem constants
#define BB    8
#define SQ    4096
#define QD    1280
#define SCTX  93
#define CD    2048
#define NH    20
#define DH    64
#define INNER 1280

// ---------------------------------------------------------------------------
// Scratch (__device__ globals; no allocs allowed)
// ---------------------------------------------------------------------------
// Q as prebuilt swizzled bf16 hi/lo tiles: per (bh, qt): 128 rows x 128B
__device__ __align__(16) unsigned char g_qh[(size_t)BB * NH * 32 * 16384];
__device__ __align__(16) unsigned char g_ql[(size_t)BB * NH * 32 * 16384];
// K as prebuilt swizzled bf16 hi/lo tiles: per bh: 96 rows x 128B
__device__ __align__(16) unsigned char g_kh[(size_t)BB * NH * 12288];
__device__ __align__(16) unsigned char g_kl[(size_t)BB * NH * 12288];
// Vt (transposed) bf16 hi/lo tiles: per bh: 64 rows x 208B
__device__ __align__(16) unsigned char g_vth[(size_t)BB * NH * 13312];
__device__ __align__(16) unsigned char g_vtl[(size_t)BB * NH * 13312];

__device__ __half g_x16 [(size_t)BB * SQ * QD];
__device__ __half g_a16 [(size_t)BB * SQ * INNER];
__device__ __half g_wq16[(size_t)INNER * QD];
__device__ __half g_wo16[(size_t)QD * INNER];
__device__ float  g_k[(size_t)BB * NH * SCTX * DH];
__device__ float  g_v[(size_t)BB * NH * SCTX * DH];

// ---------------------------------------------------------------------------
// Helpers (arch-agnostic PTX only: cp.async, ldmatrix, mma.sync)
// ---------------------------------------------------------------------------
__device__ __forceinline__ uint32_t smem_u32(const void* p) {
    uint32_t a;
    asm("{ .reg .u64 t; cvta.to.shared.u64 t, %1; cvt.u32.u64 %0, t; }"
        : "=r"(a) : "l"(p));
    return a;
}
#define CP_COMMIT() asm volatile("cp.async.commit_group;" ::: "memory")
#define CP_WAIT(n)  asm volatile("cp.async.wait_group %0;" :: "n"(n) : "memory")
#define CP_ASYNC16(dst, src) \
    asm volatile("cp.async.cg.shared.global [%0], [%1], 16;" \
                 :: "r"(dst), "l"(src) : "memory")

__device__ __forceinline__ void ldsm_x4(uint32_t addr, uint32_t& r0, uint32_t& r1,
                                        uint32_t& r2, uint32_t& r3) {
    asm volatile("ldmatrix.sync.aligned.m8n8.x4.shared.b16 {%0,%1,%2,%3}, [%4];"
                 : "=r"(r0), "=r"(r1), "=r"(r2), "=r"(r3) : "r"(addr));
}
__device__ __forceinline__ void mma_bf16(float* c, const uint32_t* a,
                                         const uint32_t* b) {
    asm volatile(
        "mma.sync.aligned.m16n8k16.row.col.f32.bf16.bf16.f32 "
        "{%0,%1,%2,%3}, {%4,%5,%6,%7}, {%8,%9}, {%0,%1,%2,%3};"
        : "+f"(c[0]), "+f"(c[1]), "+f"(c[2]), "+f"(c[3])
        : "r"(a[0]), "r"(a[1]), "r"(a[2]), "r"(a[3]), "r"(b[0]), "r"(b[1]));
}
__device__ __forceinline__ void mma_fp16(float* c, const uint32_t* a,
                                         const uint32_t* b) {
    asm volatile(
        "mma.sync.aligned.m16n8k16.row.col.f32.f16.f16.f32 "
        "{%0,%1,%2,%3}, {%4,%5,%6,%7}, {%8,%9}, {%0,%1,%2,%3};"
        : "+f"(c[0]), "+f"(c[1]), "+f"(c[2]), "+f"(c[3])
        : "r"(a[0]), "r"(a[1]), "r"(a[2]), "r"(a[3]), "r"(b[0]), "r"(b[1]));
}
__device__ __forceinline__ uint32_t packbf(float x, float y) {
    __nv_bfloat162 t = __floats2bfloat162_rn(x, y);
    return *(uint32_t*)&t;
}
__device__ __forceinline__ uint32_t packhf(float x, float y) {
    __half2 t = __floats2half2_rn(x, y);
    return *(uint32_t*)&t;
}
__device__ __forceinline__ float bfres(float x) {
    return x - __bfloat162float(__float2bfloat16(x));
}

// ---------------------------------------------------------------------------
// fp32 -> fp16 cast
// ---------------------------------------------------------------------------
__global__ void to_fp16(const float4* __restrict__ src,
                        ushort4* __restrict__ dst, int n4)
{
    for (int i = blockIdx.x * blockDim.x + threadIdx.x; i < n4;
         i += gridDim.x * blockDim.x) {
        float4 v = src[i];
        ushort4 o;
        o.x = __half_as_ushort(__float2half_rn(v.x));
        o.y = __half_as_ushort(__float2half_rn(v.y));
        o.z = __half_as_ushort(__float2half_rn(v.z));
        o.w = __half_as_ushort(__float2half_rn(v.w));
        dst[i] = o;
    }
}

// ---------------------------------------------------------------------------
// KV projections (fp32, small)
// ---------------------------------------------------------------------------
__global__ void __launch_bounds__(512) kv_proj_kernel(
    const float* __restrict__ ctx,
    const float* __restrict__ Wk,  const float* __restrict__ Wv,
    const float* __restrict__ Wki, const float* __restrict__ Wvi,
    const int*   __restrict__ nimg_p)
{
    __shared__ float cs[96][17];
    __shared__ float wk_s[64][17], wv_s[64][17], wki_s[64][17], wvi_s[64][17];

    const int tid = threadIdx.x;
    const int b   = blockIdx.y;
    const int hh  = blockIdx.x;
    const int n0  = hh * 64;
    const int eos = SCTX - *nimg_p;
    const int n   = tid & 63;
    const int g   = tid >> 6;

    float ak[12], av[12];
#pragma unroll
    for (int j = 0; j < 12; ++j) { ak[j] = 0.f; av[j] = 0.f; }

    for (int k0 = 0; k0 < CD; k0 += 16) {
        __syncthreads();
        for (int i = tid; i < 96 * 16; i += 512) {
            int s = i >> 4, kk = i & 15;
            cs[s][kk] = (s < SCTX) ? ctx[((size_t)b * SCTX + s) * CD + k0 + kk] : 0.f;
        }
        for (int i = tid; i < 64 * 16; i += 512) {
            int r = i >> 4, kk = i & 15;
            size_t gi = (size_t)(n0 + r) * CD + k0 + kk;
            wk_s [r][kk] = Wk [gi]; wv_s [r][kk] = Wv [gi];
            wki_s[r][kk] = Wki[gi]; wvi_s[r][kk] = Wvi[gi];
        }
        __syncthreads();
#pragma unroll
        for (int kk = 0; kk < 16; ++kk) {
            float wkv = wk_s[n][kk],  wvv = wv_s[n][kk];
            float wkiv = wki_s[n][kk], wviv = wvi_s[n][kk];
#pragma unroll
            for (int j = 0; j < 12; ++j) {
                int s = g * 12 + j;
                float c = cs[s][kk];
                bool txt = (s < eos);
                ak[j] = fmaf(c, txt ? wkv : wkiv, ak[j]);
                av[j] = fmaf(c, txt ? wvv : wviv, av[j]);
            }
        }
    }
    size_t base = ((size_t)(b * NH + hh) * SCTX) * DH + n;
#pragma unroll
    for (int j = 0; j < 12; ++j) {
        int s = g * 12 + j;
        if (s < SCTX) {
            g_k[base + (size_t)s * DH] = ak[j];
            g_v[base + (size_t)s * DH] = av[j];
        }
    }
}

// ---------------------------------------------------------------------------
// kv_pack: build swizzled bf16 hi/lo K tiles and transposed Vt tiles, once
// per (b,h). Grid = 160, 128 threads.
// ---------------------------------------------------------------------------
__global__ void __launch_bounds__(128) kv_pack(void)
{
    const int tid = threadIdx.x;
    const int bh  = blockIdx.x;

    // K: 96 rows x 128B swizzled
    for (int idx = tid; idx < 96 * 8; idx += 128) {
        int r = idx >> 3, cb = idx & 7;
        float4 u = {0,0,0,0}, v = {0,0,0,0};
        if (r < SCTX) {
            const float4* kp = (const float4*)(g_k + ((size_t)bh * SCTX + r) * DH + cb * 8);
            u = kp[0]; v = kp[1];
        }
        uint4 H, L;
        H.x = packbf(u.x, u.y); H.y = packbf(u.z, u.w);
        H.z = packbf(v.x, v.y); H.w = packbf(v.z, v.w);
        L.x = packbf(bfres(u.x), bfres(u.y)); L.y = packbf(bfres(u.z), bfres(u.w));
        L.z = packbf(bfres(v.x), bfres(v.y)); L.w = packbf(bfres(v.z), bfres(v.w));
        size_t off = (size_t)bh * 12288 + r * 128 + ((cb ^ (r & 7)) << 4);
        *(uint4*)(g_kh + off) = H;
        *(uint4*)(g_kl + off) = L;
    }
    // Vt: 64 rows(d) x 208B stride, 12 chunks of 16B used
    for (int idx = tid; idx < 64 * 12; idx += 128) {
        int d = idx / 12, sc = idx % 12;
        float vals[8];
#pragma unroll
        for (int j = 0; j < 8; ++j) {
            int s = sc * 8 + j;
            vals[j] = (s < SCTX) ? g_v[((size_t)bh * SCTX + s) * DH + d] : 0.f;
        }
        uint4 H, L;
        H.x = packbf(vals[0], vals[1]); H.y = packbf(vals[2], vals[3]);
        H.z = packbf(vals[4], vals[5]); H.w = packbf(vals[6], vals[7]);
        L.x = packbf(bfres(vals[0]), bfres(vals[1]));
        L.y = packbf(bfres(vals[2]), bfres(vals[3]));
        L.z = packbf(bfres(vals[4]), bfres(vals[5]));
        L.w = packbf(bfres(vals[6]), bfres(vals[7]));
        size_t off = (size_t)bh * 13312 + d * 208 + sc * 16;
        *(uint4*)(g_vth + off) = H;
        *(uint4*)(g_vtl + off) = L;
    }
}

// ---------------------------------------------------------------------------
// fp16 HMMA GEMM: C[m,n] = sum_k A[m,k]*B[n,k].
// 128x128 CTA tile, 8 warps (2m x 4n), K-chunk 64, 3-stage cp.async pipeline,
// 96KB smem -> 2 CTAs/SM. 128B rows, swizzle cb ^ (r&7) on 16B columns.
// REMAP_Q epilogue writes Q as swizzled bf16 hi/lo tiles (g_qh/g_ql).
// ---------------------------------------------------------------------------
#define GEMM_STAGES 3
#define TILE_BYTES  16384                 // 128 x 64 fp16
#define STAGE_BYTES (2 * TILE_BYTES)
#define GEMM_SMEM   (GEMM_STAGES * STAGE_BYTES)

__device__ __forceinline__ void load_tiles16(
    uint32_t sbase,
    const __half* __restrict__ A, const __half* __restrict__ B,
    int m0, int n0, int k0, int K, int tid)
{
#pragma unroll
    for (int i = 0; i < 8; ++i) {
        int idx = tid + (i << 8);            // 0..2047 16B chunks
        int mat = idx >> 10;                 // 0:A 1:B
        int r   = (idx >> 3) & 127;
        int cb  = idx & 7;
        int grow = ((mat == 0) ? m0 : n0) + r;
        const __half* base = (mat == 0) ? A : B;
        const char* src = (const char*)(base + (size_t)grow * K + k0) + (cb << 4);
        uint32_t dst = sbase + (mat << 14) + (r << 7)
                     + (uint32_t)((cb ^ (r & 7)) << 4);
        CP_ASYNC16(dst, src);
    }
}

template <bool REMAP_Q, bool HAS_BIAS>
__global__ void __launch_bounds__(256, 2) gemm_fp16(
    const __half* __restrict__ A, const __half* __restrict__ B,
    const float* __restrict__ bias, float* __restrict__ C, int K)
{
    extern __shared__ __align__(128) char smem[];
    const uint32_t sb = smem_u32(smem);
    const int tid  = threadIdx.x;
    const int wid  = tid >> 5;
    const int lane = tid & 31;
    const int mw   = wid >> 2;
    const int nw   = wid & 3;
    const int n0   = blockIdx.x << 7;
    const int m0   = blockIdx.y << 7;
    const int NCH  = K >> 6;

    // per-thread ldmatrix row/xor components (128B rows)
    uint32_t arow[4];
#pragma unroll
    for (int mi = 0; mi < 4; ++mi)
        arow[mi] = (uint32_t)(mw * 64 + mi * 16 + (lane & 15));
    uint32_t brow[2];
#pragma unroll
    for (int bt = 0; bt < 2; ++bt)
        brow[bt] = (uint32_t)(nw * 32 + bt * 16 + ((lane >> 4) << 3) + (lane & 7));
    const uint32_t cA = (uint32_t)(lane >> 4) << 4;        // 0/16
    const uint32_t cB = ((uint32_t)(lane >> 3) & 1) << 4;  // 0/16

    float acc[4][4][4];
#pragma unroll
    for (int i = 0; i < 4; ++i)
#pragma unroll
        for (int j = 0; j < 4; ++j)
#pragma unroll
            for (int v = 0; v < 4; ++v) acc[i][j][v] = 0.f;

#pragma unroll
    for (int c = 0; c < GEMM_STAGES - 1; ++c) {
        load_tiles16(sb + c * STAGE_BYTES, A, B, m0, n0, c << 6, K, tid);
        CP_COMMIT();
    }

    int s = 0;
    for (int c = 0; c < NCH; ++c) {
        CP_WAIT(1);
        __syncthreads();

        if (c + GEMM_STAGES - 1 < NCH) {
            int sn = c + GEMM_STAGES - 1;
            load_tiles16(sb + (sn % GEMM_STAGES) * STAGE_BYTES, A, B,
                         m0, n0, sn << 6, K, tid);
        }
        CP_COMMIT();

        const uint32_t bA = sb + s * STAGE_BYTES;
        const uint32_t bB = bA + TILE_BYTES;

#pragma unroll
        for (int t = 0; t < 4; ++t) {
            uint32_t a[4][4], b[4][2];
#pragma unroll
            for (int mi = 0; mi < 4; ++mi) {
                uint32_t byte = arow[mi] * 128
                    + (((uint32_t)(t * 32) + cA) ^ ((arow[mi] & 7) << 4));
                ldsm_x4(bA + byte, a[mi][0], a[mi][1], a[mi][2], a[mi][3]);
            }
#pragma unroll
            for (int bt = 0; bt < 2; ++bt) {
                uint32_t byte = brow[bt] * 128
                    + (((uint32_t)(t * 32) + cB) ^ ((brow[bt] & 7) << 4));
                ldsm_x4(bB + byte, b[bt*2][0], b[bt*2][1],
                                   b[bt*2+1][0], b[bt*2+1][1]);
            }
#pragma unroll
            for (int mi = 0; mi < 4; ++mi)
#pragma unroll
                for (int ni = 0; ni < 4; ++ni)
                    mma_fp16(acc[mi][ni], a[mi], b[ni]);
        }
        s = (s == GEMM_STAGES - 1) ? 0 : s + 1;
    }

    // epilogue
#pragma unroll
    for (int mi = 0; mi < 4; ++mi) {
        const int mbase = m0 + mw * 64 + mi * 16 + (lane >> 2);
#pragma unroll
        for (int ni = 0; ni < 4; ++ni) {
            const int n = n0 + nw * 32 + ni * 8 + (lane & 3) * 2;
            if (REMAP_Q) {
                const int h = n >> 6, d = n & 63;
#pragma unroll
                for (int rr = 0; rr < 2; ++rr) {
                    const int m  = mbase + rr * 8;
                    const int b_ = m >> 12, sq = m & 4095;
                    const int qt = sq >> 7,  r  = sq & 127;
                    const int bh = b_ * NH + h;
                    size_t off = ((size_t)(bh * 32 + qt)) * 16384
                               + r * 128 + (((d >> 3) ^ (r & 7)) << 4)
                               + (d & 7) * 2;
                    float v0 = acc[mi][ni][rr * 2], v1 = acc[mi][ni][rr * 2 + 1];
                    *(uint32_t*)(g_qh + off) = packbf(v0, v1);
                    *(uint32_t*)(g_ql + off) = packbf(bfres(v0), bfres(v1));
                }
            } else {
                float2 v0, v1;
                v0.x = acc[mi][ni][0]; v0.y = acc[mi][ni][1];
                v1.x = acc[mi][ni][2]; v1.y = acc[mi][ni][3];
                if (HAS_BIAS) {
                    float b0 = bias[n], b1 = bias[n + 1];
                    v0.x += b0; v0.y += b1; v1.x += b0; v1.y += b1;
                }
                *(float2*)(C + (size_t)mbase * QD + n) = v0;
                *(float2*)(C + (size_t)(mbase + 8) * QD + n) = v1;
            }
        }
    }
}

// ---------------------------------------------------------------------------
// HMMA flash-style two-segment attention, zero-conversion version.
// All operands prebuilt in global as the exact smem images -> cp.async only.
// ---------------------------------------------------------------------------
#define AQH  0
#define AQL  16384
#define AKH  32768
#define AKL  45056
#define AVH  57344
#define AVL  70656
#define ATTN_SMEM 83968

__global__ void __launch_bounds__(128) attn_mma(
    const float* __restrict__ scale_p, const int* __restrict__ nimg_p)
{
    extern __shared__ __align__(128) char smem[];
    const uint32_t sb = smem_u32(smem);
    const int tid  = threadIdx.x;
    const int lane = tid & 31;
    const int w    = tid >> 5;
    const int bh   = blockIdx.x;
    const int qt   = blockIdx.y;
    const int q0   = qt << 7;
    const int b    = bh / NH;
    const int h    = bh % NH;
    const int eos  = SCTX - *nimg_p;
    const float ipscale = *scale_p;

    // bulk cp.async of prebuilt tiles
    {
        const unsigned char* qbh = g_qh + ((size_t)(bh * 32 + qt)) * 16384;
        const unsigned char* qbl = g_ql + ((size_t)(bh * 32 + qt)) * 16384;
        for (uint32_t o = tid * 16; o < 16384; o += 2048) {
            CP_ASYNC16(sb + AQH + o, qbh + o);
            CP_ASYNC16(sb + AQL + o, qbl + o);
        }
        const unsigned char* kbh = g_kh + (size_t)bh * 12288;
        const unsigned char* kbl = g_kl + (size_t)bh * 12288;
        for (uint32_t o = tid * 16; o < 12288; o += 2048) {
            CP_ASYNC16(sb + AKH + o, kbh + o);
            CP_ASYNC16(sb + AKL + o, kbl + o);
        }
        const unsigned char* vbh = g_vth + (size_t)bh * 13312;
        const unsigned char* vbl = g_vtl + (size_t)bh * 13312;
        for (uint32_t o = tid * 16; o < 13312; o += 2048) {
            CP_ASYNC16(sb + AVH + o, vbh + o);
            CP_ASYNC16(sb + AVL + o, vbl + o);
        }
    }
    CP_COMMIT();
    CP_WAIT(0);
    __syncthreads();

    // QK^T
    float Lg[2][12][4];
#pragma unroll
    for (int mi = 0; mi < 2; ++mi)
#pragma unroll
        for (int j = 0; j < 12; ++j)
#pragma unroll
            for (int v = 0; v < 4; ++v) Lg[mi][j][v] = 0.f;

#pragma unroll
    for (int kc = 0; kc < 4; ++kc) {
        uint32_t qa_h[2][4], qa_l[2][4];
#pragma unroll
        for (int mi = 0; mi < 2; ++mi) {
            uint32_t row = (uint32_t)(w * 32 + mi * 16 + (lane & 15));
            uint32_t byte = row * 128
                + (((uint32_t)(kc * 32) + ((uint32_t)(lane >> 4) << 4))
                   ^ ((row & 7) << 4));
            ldsm_x4(sb + AQH + byte, qa_h[mi][0], qa_h[mi][1], qa_h[mi][2], qa_h[mi][3]);
            ldsm_x4(sb + AQL + byte, qa_l[mi][0], qa_l[mi][1], qa_l[mi][2], qa_l[mi][3]);
        }
        uint32_t kb_h[12][2], kb_l[12][2];
#pragma unroll
        for (int bt = 0; bt < 6; ++bt) {
            uint32_t row = (uint32_t)(bt * 16 + ((lane >> 4) << 3) + (lane & 7));
            uint32_t byte = row * 128
                + (((uint32_t)(kc * 32) + (((uint32_t)(lane >> 3) & 1) << 4))
                   ^ ((row & 7) << 4));
            ldsm_x4(sb + AKH + byte, kb_h[bt*2][0], kb_h[bt*2][1],
                                     kb_h[bt*2+1][0], kb_h[bt*2+1][1]);
            ldsm_x4(sb + AKL + byte, kb_l[bt*2][0], kb_l[bt*2][1],
                                     kb_l[bt*2+1][0], kb_l[bt*2+1][1]);
        }
#pragma unroll
        for (int mi = 0; mi < 2; ++mi)
#pragma unroll
            for (int j = 0; j < 12; ++j) {
                mma_bf16(Lg[mi][j], qa_h[mi], kb_h[j]);
                mma_bf16(Lg[mi][j], qa_h[mi], kb_l[j]);
                mma_bf16(Lg[mi][j], qa_l[mi], kb_h[j]);
            }
    }

    // two-segment softmax
    const int c0 = 2 * (lane & 3);
#pragma unroll
    for (int mi = 0; mi < 2; ++mi) {
#pragma unroll
        for (int half = 0; half < 2; ++half) {
            float mx1 = -1e30f, mx2 = -1e30f;
#pragma unroll
            for (int j = 0; j < 12; ++j)
#pragma unroll
                for (int u = 0; u < 2; ++u) {
                    int col = j * 8 + c0 + u;
                    float v = Lg[mi][j][half * 2 + u] * 0.125f;
                    Lg[mi][j][half * 2 + u] = v;
                    if (col < SCTX) {
                        if (col < eos) mx1 = fmaxf(mx1, v);
                        else           mx2 = fmaxf(mx2, v);
                    }
                }
            mx1 = fmaxf(mx1, __shfl_xor_sync(0xffffffffu, mx1, 1));
            mx1 = fmaxf(mx1, __shfl_xor_sync(0xffffffffu, mx1, 2));
            mx2 = fmaxf(mx2, __shfl_xor_sync(0xffffffffu, mx2, 1));
            mx2 = fmaxf(mx2, __shfl_xor_sync(0xffffffffu, mx2, 2));
            float s1 = 0.f, s2 = 0.f;
#pragma unroll
            for (int j = 0; j < 12; ++j)
#pragma unroll
                for (int u = 0; u < 2; ++u) {
                    int col = j * 8 + c0 + u;
                    float v = Lg[mi][j][half * 2 + u];
                    if (col < SCTX) {
                        if (col < eos) s1 += __expf(v - mx1);
                        else           s2 += __expf(v - mx2);
                    }
                }
            s1 += __shfl_xor_sync(0xffffffffu, s1, 1);
            s1 += __shfl_xor_sync(0xffffffffu, s1, 2);
            s2 += __shfl_xor_sync(0xffffffffu, s2, 1);
            s2 += __shfl_xor_sync(0xffffffffu, s2, 2);
            float w1 = (s1 > 0.f) ? 1.f / s1 : 0.f;
            float w2 = (s2 > 0.f) ? ipscale / s2 : 0.f;
#pragma unroll
            for (int j = 0; j < 12; ++j)
#pragma unroll
                for (int u = 0; u < 2; ++u) {
                    int col = j * 8 + c0 + u;
                    float v = Lg[mi][j][half * 2 + u];
                    float p = 0.f;
                    if (col < SCTX)
                        p = (col < eos) ? __expf(v - mx1) * w1
                                        : __expf(v - mx2) * w2;
                    Lg[mi][j][half * 2 + u] = p;
                }
        }
    }

    // P * V
    float o[2][8][4];
#pragma unroll
    for (int mi = 0; mi < 2; ++mi)
#pragma unroll
        for (int nd = 0; nd < 8; ++nd)
#pragma unroll
            for (int v = 0; v < 4; ++v) o[mi][nd][v] = 0.f;

#pragma unroll
    for (int kc = 0; kc < 6; ++kc) {
        uint32_t vb_h[8][2], vb_l[8][2];
#pragma unroll
        for (int dt = 0; dt < 4; ++dt) {
            uint32_t row = (uint32_t)(dt * 16 + ((lane >> 4) << 3) + (lane & 7));
            uint32_t byte = row * 208 + (uint32_t)(kc * 32)
                          + (((uint32_t)(lane >> 3) & 1) << 4);
            ldsm_x4(sb + AVH + byte, vb_h[dt*2][0], vb_h[dt*2][1],
                                     vb_h[dt*2+1][0], vb_h[dt*2+1][1]);
            ldsm_x4(sb + AVL + byte, vb_l[dt*2][0], vb_l[dt*2][1],
                                     vb_l[dt*2+1][0], vb_l[dt*2+1][1]);
        }
#pragma unroll
        for (int mi = 0; mi < 2; ++mi) {
            const float* p0 = Lg[mi][2 * kc];
            const float* p1 = Lg[mi][2 * kc + 1];
            uint32_t pa_h[4], pa_l[4];
            pa_h[0] = packbf(p0[0], p0[1]);
            pa_h[1] = packbf(p0[2], p0[3]);
            pa_h[2] = packbf(p1[0], p1[1]);
            pa_h[3] = packbf(p1[2], p1[3]);
            pa_l[0] = packbf(bfres(p0[0]), bfres(p0[1]));
            pa_l[1] = packbf(bfres(p0[2]), bfres(p0[3]));
            pa_l[2] = packbf(bfres(p1[0]), bfres(p1[1]));
            pa_l[3] = packbf(bfres(p1[2]), bfres(p1[3]));
#pragma unroll
            for (int nd = 0; nd < 8; ++nd) {
                mma_bf16(o[mi][nd], pa_h, vb_h[nd]);
                mma_bf16(o[mi][nd], pa_h, vb_l[nd]);
                mma_bf16(o[mi][nd], pa_l, vb_h[nd]);
            }
        }
    }

    // epilogue: fp16 out
#pragma unroll
    for (int mi = 0; mi < 2; ++mi) {
        const int r0 = q0 + w * 32 + mi * 16 + (lane >> 2);
#pragma unroll
        for (int nd = 0; nd < 8; ++nd) {
            const int d = nd * 8 + c0;
            size_t base0 = ((size_t)b * SQ + r0) * INNER + h * DH + d;
            size_t base1 = base0 + (size_t)8 * INNER;
            *(uint32_t*)(g_a16 + base0) = packhf(o[mi][nd][0], o[mi][nd][1]);
            *(uint32_t*)(g_a16 + base1) = packhf(o[mi][nd][2], o[mi][nd][3]);
        }
    }
}

// ---------------------------------------------------------------------------
// Launch: x, context, scale, num_img_token, Wq, Wk, Wv, Wk_ip, Wv_ip, Wout, b_out
// ---------------------------------------------------------------------------
extern "C" void kernel_launch(void* const* d_in, const int* in_sizes, int n_in,
                              void* d_out, int out_size)
{
    const float* x     = (const float*)d_in[0];
    const float* ctx   = (const float*)d_in[1];
    const float* scale = (const float*)d_in[2];
    const int*   nimg  = (const int*)  d_in[3];
    const float* Wq    = (const float*)d_in[4];
    const float* Wout  = (const float*)d_in[9];
    const float* bout  = (const float*)d_in[10];
    float*       out   = (float*)d_out;

    __half *x16, *a16, *wq16, *wo16;
    cudaGetSymbolAddress((void**)&x16,  g_x16);
    cudaGetSymbolAddress((void**)&a16,  g_a16);
    cudaGetSymbolAddress((void**)&wq16, g_wq16);
    cudaGetSymbolAddress((void**)&wo16, g_wo16);

    cudaFuncSetAttribute(attn_mma,
        cudaFuncAttributeMaxDynamicSharedMemorySize, ATTN_SMEM);
    cudaFuncSetAttribute(gemm_fp16<true, false>,
        cudaFuncAttributeMaxDynamicSharedMemorySize, GEMM_SMEM);
    cudaFuncSetAttribute(gemm_fp16<false, true>,
        cudaFuncAttributeMaxDynamicSharedMemorySize, GEMM_SMEM);

    // conversions
    to_fp16<<<4096, 256>>>((const float4*)x, (ushort4*)x16,
                           (int)((size_t)BB * SQ * QD / 4));
    to_fp16<<<1600, 256>>>((const float4*)Wq, (ushort4*)wq16, INNER * QD / 4);
    to_fp16<<<1600, 256>>>((const float4*)Wout, (ushort4*)wo16, QD * INNER / 4);

    // K/V projections + packing into attention-ready tiles
    kv_proj_kernel<<<dim3(NH, BB), 512>>>(ctx,
        (const float*)d_in[5], (const float*)d_in[6],
        (const float*)d_in[7], (const float*)d_in[8], nimg);
    kv_pack<<<BB * NH, 128>>>();

    // Q projection (fp16 HMMA) -> swizzled bf16 hi/lo Q tiles
    gemm_fp16<true, false><<<dim3(INNER / 128, (BB * SQ) / 128), 256, GEMM_SMEM>>>(
        x16, wq16, nullptr, nullptr, QD);

    // flash-style two-segment attention (zero-conversion) -> fp16
    attn_mma<<<dim3(BB * NH, SQ / 128), 128, ATTN_SMEM>>>(scale, nimg);

    // output projection + bias (fp16 HMMA)
    gemm_fp16<false, true><<<dim3(QD / 128, (BB * SQ) / 128), 256, GEMM_SMEM>>>(
        a16, wo16, bout, out, INNER);
}

// round 8
// speedup vs baseline: 3.8248x; 1.0753x over previous
#include <cuda_runtime.h>
#include <cuda_bf16.h>
#include <cuda_fp16.h>
#include <cstdint>
#include <cstddef>

// Problem constants
#define BB    8
#define SQ    4096
#define QD    1280
#define SCTX  93
#define CD    2048
#define NH    20
#define DH    64
#define INNER 1280

// ---------------------------------------------------------------------------
// Scratch (__device__ globals; no allocs allowed)
// ---------------------------------------------------------------------------
// Q as prebuilt swizzled fp16 tiles: per (bh, qt): 128 rows x 128B
__device__ __align__(16) unsigned char g_qt[(size_t)BB * NH * 32 * 16384];
// K as prebuilt swizzled fp16 tiles: per bh: 96 rows x 128B
__device__ __align__(16) unsigned char g_kt[(size_t)BB * NH * 12288];
// Vt (transposed) fp16 tiles: per bh: 64 rows x 208B
__device__ __align__(16) unsigned char g_vt[(size_t)BB * NH * 13312];

__device__ __half g_x16 [(size_t)BB * SQ * QD];
__device__ __half g_a16 [(size_t)BB * SQ * INNER];
__device__ __half g_wq16[(size_t)INNER * QD];
__device__ __half g_wo16[(size_t)QD * INNER];
__device__ float  g_k[(size_t)BB * NH * SCTX * DH];
__device__ float  g_v[(size_t)BB * NH * SCTX * DH];

// ---------------------------------------------------------------------------
// Helpers (arch-agnostic PTX only: cp.async, ldmatrix, mma.sync)
// ---------------------------------------------------------------------------
__device__ __forceinline__ uint32_t smem_u32(const void* p) {
    uint32_t a;
    asm("{ .reg .u64 t; cvta.to.shared.u64 t, %1; cvt.u32.u64 %0, t; }"
        : "=r"(a) : "l"(p));
    return a;
}
#define CP_COMMIT() asm volatile("cp.async.commit_group;" ::: "memory")
#define CP_WAIT(n)  asm volatile("cp.async.wait_group %0;" :: "n"(n) : "memory")
#define CP_ASYNC16(dst, src) \
    asm volatile("cp.async.cg.shared.global [%0], [%1], 16;" \
                 :: "r"(dst), "l"(src) : "memory")

__device__ __forceinline__ void ldsm_x4(uint32_t addr, uint32_t& r0, uint32_t& r1,
                                        uint32_t& r2, uint32_t& r3) {
    asm volatile("ldmatrix.sync.aligned.m8n8.x4.shared.b16 {%0,%1,%2,%3}, [%4];"
                 : "=r"(r0), "=r"(r1), "=r"(r2), "=r"(r3) : "r"(addr));
}
__device__ __forceinline__ void mma_fp16(float* c, const uint32_t* a,
                                         const uint32_t* b) {
    asm volatile(
        "mma.sync.aligned.m16n8k16.row.col.f32.f16.f16.f32 "
        "{%0,%1,%2,%3}, {%4,%5,%6,%7}, {%8,%9}, {%0,%1,%2,%3};"
        : "+f"(c[0]), "+f"(c[1]), "+f"(c[2]), "+f"(c[3])
        : "r"(a[0]), "r"(a[1]), "r"(a[2]), "r"(a[3]), "r"(b[0]), "r"(b[1]));
}
__device__ __forceinline__ uint32_t packhf(float x, float y) {
    __half2 t = __floats2half2_rn(x, y);
    return *(uint32_t*)&t;
}

// ---------------------------------------------------------------------------
// fp32 -> fp16 cast
// ---------------------------------------------------------------------------
__global__ void to_fp16(const float4* __restrict__ src,
                        ushort4* __restrict__ dst, int n4)
{
    for (int i = blockIdx.x * blockDim.x + threadIdx.x; i < n4;
         i += gridDim.x * blockDim.x) {
        float4 v = src[i];
        ushort4 o;
        o.x = __half_as_ushort(__float2half_rn(v.x));
        o.y = __half_as_ushort(__float2half_rn(v.y));
        o.z = __half_as_ushort(__float2half_rn(v.z));
        o.w = __half_as_ushort(__float2half_rn(v.w));
        dst[i] = o;
    }
}

// ---------------------------------------------------------------------------
// KV projections (fp32, small)
// ---------------------------------------------------------------------------
__global__ void __launch_bounds__(512) kv_proj_kernel(
    const float* __restrict__ ctx,
    const float* __restrict__ Wk,  const float* __restrict__ Wv,
    const float* __restrict__ Wki, const float* __restrict__ Wvi,
    const int*   __restrict__ nimg_p)
{
    __shared__ float cs[96][17];
    __shared__ float wk_s[64][17], wv_s[64][17], wki_s[64][17], wvi_s[64][17];

    const int tid = threadIdx.x;
    const int b   = blockIdx.y;
    const int hh  = blockIdx.x;
    const int n0  = hh * 64;
    const int eos = SCTX - *nimg_p;
    const int n   = tid & 63;
    const int g   = tid >> 6;

    float ak[12], av[12];
#pragma unroll
    for (int j = 0; j < 12; ++j) { ak[j] = 0.f; av[j] = 0.f; }

    for (int k0 = 0; k0 < CD; k0 += 16) {
        __syncthreads();
        for (int i = tid; i < 96 * 16; i += 512) {
            int s = i >> 4, kk = i & 15;
            cs[s][kk] = (s < SCTX) ? ctx[((size_t)b * SCTX + s) * CD + k0 + kk] : 0.f;
        }
        for (int i = tid; i < 64 * 16; i += 512) {
            int r = i >> 4, kk = i & 15;
            size_t gi = (size_t)(n0 + r) * CD + k0 + kk;
            wk_s [r][kk] = Wk [gi]; wv_s [r][kk] = Wv [gi];
            wki_s[r][kk] = Wki[gi]; wvi_s[r][kk] = Wvi[gi];
        }
        __syncthreads();
#pragma unroll
        for (int kk = 0; kk < 16; ++kk) {
            float wkv = wk_s[n][kk],  wvv = wv_s[n][kk];
            float wkiv = wki_s[n][kk], wviv = wvi_s[n][kk];
#pragma unroll
            for (int j = 0; j < 12; ++j) {
                int s = g * 12 + j;
                float c = cs[s][kk];
                bool txt = (s < eos);
                ak[j] = fmaf(c, txt ? wkv : wkiv, ak[j]);
                av[j] = fmaf(c, txt ? wvv : wviv, av[j]);
            }
        }
    }
    size_t base = ((size_t)(b * NH + hh) * SCTX) * DH + n;
#pragma unroll
    for (int j = 0; j < 12; ++j) {
        int s = g * 12 + j;
        if (s < SCTX) {
            g_k[base + (size_t)s * DH] = ak[j];
            g_v[base + (size_t)s * DH] = av[j];
        }
    }
}

// ---------------------------------------------------------------------------
// kv_pack: build swizzled fp16 K tiles and transposed Vt tiles per (b,h).
// ---------------------------------------------------------------------------
__global__ void __launch_bounds__(128) kv_pack(void)
{
    const int tid = threadIdx.x;
    const int bh  = blockIdx.x;

    // K: 96 rows x 128B swizzled
    for (int idx = tid; idx < 96 * 8; idx += 128) {
        int r = idx >> 3, cb = idx & 7;
        float4 u = {0,0,0,0}, v = {0,0,0,0};
        if (r < SCTX) {
            const float4* kp = (const float4*)(g_k + ((size_t)bh * SCTX + r) * DH + cb * 8);
            u = kp[0]; v = kp[1];
        }
        uint4 H;
        H.x = packhf(u.x, u.y); H.y = packhf(u.z, u.w);
        H.z = packhf(v.x, v.y); H.w = packhf(v.z, v.w);
        size_t off = (size_t)bh * 12288 + r * 128 + ((cb ^ (r & 7)) << 4);
        *(uint4*)(g_kt + off) = H;
    }
    // Vt: 64 rows(d) x 208B stride, 12 chunks of 16B used
    for (int idx = tid; idx < 64 * 12; idx += 128) {
        int d = idx / 12, sc = idx % 12;
        float vals[8];
#pragma unroll
        for (int j = 0; j < 8; ++j) {
            int s = sc * 8 + j;
            vals[j] = (s < SCTX) ? g_v[((size_t)bh * SCTX + s) * DH + d] : 0.f;
        }
        uint4 H;
        H.x = packhf(vals[0], vals[1]); H.y = packhf(vals[2], vals[3]);
        H.z = packhf(vals[4], vals[5]); H.w = packhf(vals[6], vals[7]);
        size_t off = (size_t)bh * 13312 + d * 208 + sc * 16;
        *(uint4*)(g_vt + off) = H;
    }
}

// ---------------------------------------------------------------------------
// fp16 HMMA GEMM: C[m,n] = sum_k A[m,k]*B[n,k].
// 128x128 CTA tile, 8 warps (2m x 4n), K-chunk 64, 3-stage cp.async pipeline,
// 96KB smem -> 2 CTAs/SM. 128B rows, swizzle cb ^ (r&7) on 16B columns.
// REMAP_Q epilogue writes Q as swizzled fp16 tiles (g_qt).
// ---------------------------------------------------------------------------
#define GEMM_STAGES 3
#define TILE_BYTES  16384                 // 128 x 64 fp16
#define STAGE_BYTES (2 * TILE_BYTES)
#define GEMM_SMEM   (GEMM_STAGES * STAGE_BYTES)

__device__ __forceinline__ void load_tiles16(
    uint32_t sbase,
    const __half* __restrict__ A, const __half* __restrict__ B,
    int m0, int n0, int k0, int K, int tid)
{
#pragma unroll
    for (int i = 0; i < 8; ++i) {
        int idx = tid + (i << 8);            // 0..2047 16B chunks
        int mat = idx >> 10;                 // 0:A 1:B
        int r   = (idx >> 3) & 127;
        int cb  = idx & 7;
        int grow = ((mat == 0) ? m0 : n0) + r;
        const __half* base = (mat == 0) ? A : B;
        const char* src = (const char*)(base + (size_t)grow * K + k0) + (cb << 4);
        uint32_t dst = sbase + (mat << 14) + (r << 7)
                     + (uint32_t)((cb ^ (r & 7)) << 4);
        CP_ASYNC16(dst, src);
    }
}

template <bool REMAP_Q, bool HAS_BIAS>
__global__ void __launch_bounds__(256, 2) gemm_fp16(
    const __half* __restrict__ A, const __half* __restrict__ B,
    const float* __restrict__ bias, float* __restrict__ C, int K)
{
    extern __shared__ __align__(128) char smem[];
    const uint32_t sb = smem_u32(smem);
    const int tid  = threadIdx.x;
    const int wid  = tid >> 5;
    const int lane = tid & 31;
    const int mw   = wid >> 2;
    const int nw   = wid & 3;
    const int n0   = blockIdx.x << 7;
    const int m0   = blockIdx.y << 7;
    const int NCH  = K >> 6;

    uint32_t arow[4];
#pragma unroll
    for (int mi = 0; mi < 4; ++mi)
        arow[mi] = (uint32_t)(mw * 64 + mi * 16 + (lane & 15));
    uint32_t brow[2];
#pragma unroll
    for (int bt = 0; bt < 2; ++bt)
        brow[bt] = (uint32_t)(nw * 32 + bt * 16 + ((lane >> 4) << 3) + (lane & 7));
    const uint32_t cA = (uint32_t)(lane >> 4) << 4;
    const uint32_t cB = ((uint32_t)(lane >> 3) & 1) << 4;

    float acc[4][4][4];
#pragma unroll
    for (int i = 0; i < 4; ++i)
#pragma unroll
        for (int j = 0; j < 4; ++j)
#pragma unroll
            for (int v = 0; v < 4; ++v) acc[i][j][v] = 0.f;

#pragma unroll
    for (int c = 0; c < GEMM_STAGES - 1; ++c) {
        load_tiles16(sb + c * STAGE_BYTES, A, B, m0, n0, c << 6, K, tid);
        CP_COMMIT();
    }

    int s = 0;
    for (int c = 0; c < NCH; ++c) {
        CP_WAIT(1);
        __syncthreads();

        if (c + GEMM_STAGES - 1 < NCH) {
            int sn = c + GEMM_STAGES - 1;
            load_tiles16(sb + (sn % GEMM_STAGES) * STAGE_BYTES, A, B,
                         m0, n0, sn << 6, K, tid);
        }
        CP_COMMIT();

        const uint32_t bA = sb + s * STAGE_BYTES;
        const uint32_t bB = bA + TILE_BYTES;

#pragma unroll
        for (int t = 0; t < 4; ++t) {
            uint32_t a[4][4], b[4][2];
#pragma unroll
            for (int mi = 0; mi < 4; ++mi) {
                uint32_t byte = arow[mi] * 128
                    + (((uint32_t)(t * 32) + cA) ^ ((arow[mi] & 7) << 4));
                ldsm_x4(bA + byte, a[mi][0], a[mi][1], a[mi][2], a[mi][3]);
            }
#pragma unroll
            for (int bt = 0; bt < 2; ++bt) {
                uint32_t byte = brow[bt] * 128
                    + (((uint32_t)(t * 32) + cB) ^ ((brow[bt] & 7) << 4));
                ldsm_x4(bB + byte, b[bt*2][0], b[bt*2][1],
                                   b[bt*2+1][0], b[bt*2+1][1]);
            }
#pragma unroll
            for (int mi = 0; mi < 4; ++mi)
#pragma unroll
                for (int ni = 0; ni < 4; ++ni)
                    mma_fp16(acc[mi][ni], a[mi], b[ni]);
        }
        s = (s == GEMM_STAGES - 1) ? 0 : s + 1;
    }

    // epilogue
#pragma unroll
    for (int mi = 0; mi < 4; ++mi) {
        const int mbase = m0 + mw * 64 + mi * 16 + (lane >> 2);
#pragma unroll
        for (int ni = 0; ni < 4; ++ni) {
            const int n = n0 + nw * 32 + ni * 8 + (lane & 3) * 2;
            if (REMAP_Q) {
                const int h = n >> 6, d = n & 63;
#pragma unroll
                for (int rr = 0; rr < 2; ++rr) {
                    const int m  = mbase + rr * 8;
                    const int b_ = m >> 12, sq = m & 4095;
                    const int qt = sq >> 7,  r  = sq & 127;
                    const int bh = b_ * NH + h;
                    size_t off = ((size_t)(bh * 32 + qt)) * 16384
                               + r * 128 + (((d >> 3) ^ (r & 7)) << 4)
                               + (d & 7) * 2;
                    *(uint32_t*)(g_qt + off) =
                        packhf(acc[mi][ni][rr * 2], acc[mi][ni][rr * 2 + 1]);
                }
            } else {
                float2 v0, v1;
                v0.x = acc[mi][ni][0]; v0.y = acc[mi][ni][1];
                v1.x = acc[mi][ni][2]; v1.y = acc[mi][ni][3];
                if (HAS_BIAS) {
                    float b0 = bias[n], b1 = bias[n + 1];
                    v0.x += b0; v0.y += b1; v1.x += b0; v1.y += b1;
                }
                *(float2*)(C + (size_t)mbase * QD + n) = v0;
                *(float2*)(C + (size_t)(mbase + 8) * QD + n) = v1;
            }
        }
    }
}

// ---------------------------------------------------------------------------
// fp16 single-pass flash-style two-segment attention.
// All operands prebuilt in global as the exact smem images -> cp.async only.
// smem: Q 16KB + K 12KB + Vt 13KB = 41KB -> ~5 CTAs/SM.
// ---------------------------------------------------------------------------
#define AQ  0
#define AK  16384
#define AV  28672
#define ATTN_SMEM 41984

__global__ void __launch_bounds__(128) attn_mma(
    const float* __restrict__ scale_p, const int* __restrict__ nimg_p)
{
    extern __shared__ __align__(128) char smem[];
    const uint32_t sb = smem_u32(smem);
    const int tid  = threadIdx.x;
    const int lane = tid & 31;
    const int w    = tid >> 5;
    const int bh   = blockIdx.x;
    const int qt   = blockIdx.y;
    const int q0   = qt << 7;
    const int b    = bh / NH;
    const int h    = bh % NH;
    const int eos  = SCTX - *nimg_p;
    const float ipscale = *scale_p;

    // bulk cp.async of prebuilt fp16 tiles
    {
        const unsigned char* qb = g_qt + ((size_t)(bh * 32 + qt)) * 16384;
        for (uint32_t o = tid * 16; o < 16384; o += 2048)
            CP_ASYNC16(sb + AQ + o, qb + o);
        const unsigned char* kb = g_kt + (size_t)bh * 12288;
        for (uint32_t o = tid * 16; o < 12288; o += 2048)
            CP_ASYNC16(sb + AK + o, kb + o);
        const unsigned char* vb = g_vt + (size_t)bh * 13312;
        for (uint32_t o = tid * 16; o < 13312; o += 2048)
            CP_ASYNC16(sb + AV + o, vb + o);
    }
    CP_COMMIT();
    CP_WAIT(0);
    __syncthreads();

    // QK^T
    float Lg[2][12][4];
#pragma unroll
    for (int mi = 0; mi < 2; ++mi)
#pragma unroll
        for (int j = 0; j < 12; ++j)
#pragma unroll
            for (int v = 0; v < 4; ++v) Lg[mi][j][v] = 0.f;

#pragma unroll
    for (int kc = 0; kc < 4; ++kc) {
        uint32_t qa[2][4];
#pragma unroll
        for (int mi = 0; mi < 2; ++mi) {
            uint32_t row = (uint32_t)(w * 32 + mi * 16 + (lane & 15));
            uint32_t byte = row * 128
                + (((uint32_t)(kc * 32) + ((uint32_t)(lane >> 4) << 4))
                   ^ ((row & 7) << 4));
            ldsm_x4(sb + AQ + byte, qa[mi][0], qa[mi][1], qa[mi][2], qa[mi][3]);
        }
        uint32_t kb[12][2];
#pragma unroll
        for (int bt = 0; bt < 6; ++bt) {
            uint32_t row = (uint32_t)(bt * 16 + ((lane >> 4) << 3) + (lane & 7));
            uint32_t byte = row * 128
                + (((uint32_t)(kc * 32) + (((uint32_t)(lane >> 3) & 1) << 4))
                   ^ ((row & 7) << 4));
            ldsm_x4(sb + AK + byte, kb[bt*2][0], kb[bt*2][1],
                                    kb[bt*2+1][0], kb[bt*2+1][1]);
        }
#pragma unroll
        for (int mi = 0; mi < 2; ++mi)
#pragma unroll
            for (int j = 0; j < 12; ++j)
                mma_fp16(Lg[mi][j], qa[mi], kb[j]);
    }

    // two-segment softmax
    const int c0 = 2 * (lane & 3);
#pragma unroll
    for (int mi = 0; mi < 2; ++mi) {
#pragma unroll
        for (int half = 0; half < 2; ++half) {
            float mx1 = -1e30f, mx2 = -1e30f;
#pragma unroll
            for (int j = 0; j < 12; ++j)
#pragma unroll
                for (int u = 0; u < 2; ++u) {
                    int col = j * 8 + c0 + u;
                    float v = Lg[mi][j][half * 2 + u] * 0.125f;
                    Lg[mi][j][half * 2 + u] = v;
                    if (col < SCTX) {
                        if (col < eos) mx1 = fmaxf(mx1, v);
                        else           mx2 = fmaxf(mx2, v);
                    }
                }
            mx1 = fmaxf(mx1, __shfl_xor_sync(0xffffffffu, mx1, 1));
            mx1 = fmaxf(mx1, __shfl_xor_sync(0xffffffffu, mx1, 2));
            mx2 = fmaxf(mx2, __shfl_xor_sync(0xffffffffu, mx2, 1));
            mx2 = fmaxf(mx2, __shfl_xor_sync(0xffffffffu, mx2, 2));
            float s1 = 0.f, s2 = 0.f;
#pragma unroll
            for (int j = 0; j < 12; ++j)
#pragma unroll
                for (int u = 0; u < 2; ++u) {
                    int col = j * 8 + c0 + u;
                    float v = Lg[mi][j][half * 2 + u];
                    if (col < SCTX) {
                        if (col < eos) s1 += __expf(v - mx1);
                        else           s2 += __expf(v - mx2);
                    }
                }
            s1 += __shfl_xor_sync(0xffffffffu, s1, 1);
            s1 += __shfl_xor_sync(0xffffffffu, s1, 2);
            s2 += __shfl_xor_sync(0xffffffffu, s2, 1);
            s2 += __shfl_xor_sync(0xffffffffu, s2, 2);
            float w1 = (s1 > 0.f) ? 1.f / s1 : 0.f;
            float w2 = (s2 > 0.f) ? ipscale / s2 : 0.f;
#pragma unroll
            for (int j = 0; j < 12; ++j)
#pragma unroll
                for (int u = 0; u < 2; ++u) {
                    int col = j * 8 + c0 + u;
                    float v = Lg[mi][j][half * 2 + u];
                    float p = 0.f;
                    if (col < SCTX)
                        p = (col < eos) ? __expf(v - mx1) * w1
                                        : __expf(v - mx2) * w2;
                    Lg[mi][j][half * 2 + u] = p;
                }
        }
    }

    // P * V
    float o[2][8][4];
#pragma unroll
    for (int mi = 0; mi < 2; ++mi)
#pragma unroll
        for (int nd = 0; nd < 8; ++nd)
#pragma unroll
            for (int v = 0; v < 4; ++v) o[mi][nd][v] = 0.f;

#pragma unroll
    for (int kc = 0; kc < 6; ++kc) {
        uint32_t vb[8][2];
#pragma unroll
        for (int dt = 0; dt < 4; ++dt) {
            uint32_t row = (uint32_t)(dt * 16 + ((lane >> 4) << 3) + (lane & 7));
            uint32_t byte = row * 208 + (uint32_t)(kc * 32)
                          + (((uint32_t)(lane >> 3) & 1) << 4);
            ldsm_x4(sb + AV + byte, vb[dt*2][0], vb[dt*2][1],
                                    vb[dt*2+1][0], vb[dt*2+1][1]);
        }
#pragma unroll
        for (int mi = 0; mi < 2; ++mi) {
            const float* p0 = Lg[mi][2 * kc];
            const float* p1 = Lg[mi][2 * kc + 1];
            uint32_t pa[4];
            pa[0] = packhf(p0[0], p0[1]);
            pa[1] = packhf(p0[2], p0[3]);
            pa[2] = packhf(p1[0], p1[1]);
            pa[3] = packhf(p1[2], p1[3]);
#pragma unroll
            for (int nd = 0; nd < 8; ++nd)
                mma_fp16(o[mi][nd], pa, vb[nd]);
        }
    }

    // epilogue: fp16 out
#pragma unroll
    for (int mi = 0; mi < 2; ++mi) {
        const int r0 = q0 + w * 32 + mi * 16 + (lane >> 2);
#pragma unroll
        for (int nd = 0; nd < 8; ++nd) {
            const int d = nd * 8 + c0;
            size_t base0 = ((size_t)b * SQ + r0) * INNER + h * DH + d;
            size_t base1 = base0 + (size_t)8 * INNER;
            *(uint32_t*)(g_a16 + base0) = packhf(o[mi][nd][0], o[mi][nd][1]);
            *(uint32_t*)(g_a16 + base1) = packhf(o[mi][nd][2], o[mi][nd][3]);
        }
    }
}

// ---------------------------------------------------------------------------
// Launch: x, context, scale, num_img_token, Wq, Wk, Wv, Wk_ip, Wv_ip, Wout, b_out
// ---------------------------------------------------------------------------
extern "C" void kernel_launch(void* const* d_in, const int* in_sizes, int n_in,
                              void* d_out, int out_size)
{
    const float* x     = (const float*)d_in[0];
    const float* ctx   = (const float*)d_in[1];
    const float* scale = (const float*)d_in[2];
    const int*   nimg  = (const int*)  d_in[3];
    const float* Wq    = (const float*)d_in[4];
    const float* Wout  = (const float*)d_in[9];
    const float* bout  = (const float*)d_in[10];
    float*       out   = (float*)d_out;

    __half *x16, *a16, *wq16, *wo16;
    cudaGetSymbolAddress((void**)&x16,  g_x16);
    cudaGetSymbolAddress((void**)&a16,  g_a16);
    cudaGetSymbolAddress((void**)&wq16, g_wq16);
    cudaGetSymbolAddress((void**)&wo16, g_wo16);

    cudaFuncSetAttribute(attn_mma,
        cudaFuncAttributeMaxDynamicSharedMemorySize, ATTN_SMEM);
    cudaFuncSetAttribute(gemm_fp16<true, false>,
        cudaFuncAttributeMaxDynamicSharedMemorySize, GEMM_SMEM);
    cudaFuncSetAttribute(gemm_fp16<false, true>,
        cudaFuncAttributeMaxDynamicSharedMemorySize, GEMM_SMEM);

    // conversions
    to_fp16<<<4096, 256>>>((const float4*)x, (ushort4*)x16,
                           (int)((size_t)BB * SQ * QD / 4));
    to_fp16<<<1600, 256>>>((const float4*)Wq, (ushort4*)wq16, INNER * QD / 4);
    to_fp16<<<1600, 256>>>((const float4*)Wout, (ushort4*)wo16, QD * INNER / 4);

    // K/V projections + packing into attention-ready fp16 tiles
    kv_proj_kernel<<<dim3(NH, BB), 512>>>(ctx,
        (const float*)d_in[5], (const float*)d_in[6],
        (const float*)d_in[7], (const float*)d_in[8], nimg);
    kv_pack<<<BB * NH, 128>>>();

    // Q projection (fp16 HMMA) -> swizzled fp16 Q tiles
    gemm_fp16<true, false><<<dim3(INNER / 128, (BB * SQ) / 128), 256, GEMM_SMEM>>>(
        x16, wq16, nullptr, nullptr, QD);

    // fp16 single-pass flash attention -> fp16
    attn_mma<<<dim3(BB * NH, SQ / 128), 128, ATTN_SMEM>>>(scale, nimg);

    // output projection + bias (fp16 HMMA)
    gemm_fp16<false, true><<<dim3(QD / 128, (BB * SQ) / 128), 256, GEMM_SMEM>>>(
        a16, wo16, bout, out, INNER);
}